// round 2
// baseline (speedup 1.0000x reference)
#include <cuda_runtime.h>
#include <math.h>
#include <stdint.h>

#define NB      2
#define LQ      8192
#define LEN_IN  149760
#define DM      256
#define NHEADS  8
#define NLEV    4
#define NPTS    4
#define DHEAD   32

// ---------------- scratch (device globals; no cudaMalloc allowed) ----------
__device__ float g_value[(size_t)NB * LEN_IN * DM];                       // 306 MB
__device__ float g_off  [(size_t)NB * LQ * (NHEADS * NLEV * NPTS * 3)];  // 25 MB
__device__ float g_attn [(size_t)NB * LQ * (NHEADS * NLEV * NPTS)];      // 8 MB
__device__ float g_mid  [(size_t)NB * LQ * DM];                          // 16 MB

// ---------------- packed f32x2 helpers -------------------------------------
__device__ __forceinline__ unsigned long long pack2(float lo, float hi) {
    unsigned long long r;
    asm("mov.b64 %0, {%1, %2};" : "=l"(r) : "f"(lo), "f"(hi));
    return r;
}
__device__ __forceinline__ void unpack2(unsigned long long v, float& lo, float& hi) {
    asm("mov.b64 {%0, %1}, %2;" : "=f"(lo), "=f"(hi) : "l"(v));
}
__device__ __forceinline__ void fma2(unsigned long long& acc,
                                     unsigned long long a,
                                     unsigned long long b) {
    asm("fma.rn.f32x2 %0, %1, %2, %0;" : "+l"(acc) : "l"(a), "l"(b));
}

// ---------------- fp32 GEMM via packed FFMA2: C = A(MxK)*B(KxN) + bias -----
// BM=BN=128, BK=8, 256 threads. Per-thread 8x8 tile stored as 4x8 f32x2
// pairs (pairs along M). A pairs load directly from SMEM as b64; B is stored
// duplicated-to-pairs in SMEM so the inner loop has zero pack instructions.
// Requires M%128==0, N%128==0, K%8==0 (true for all 4 GEMMs here).
__global__ __launch_bounds__(256) void sgemm_bias_kernel(
    const float* __restrict__ A, const float* __restrict__ B,
    const float* __restrict__ bias, float* __restrict__ C,
    int M, int N, int K)
{
    const int BM = 128, BN = 128, BK = 8;
    __shared__ float              As [BK][BM];          // 4 KB
    __shared__ unsigned long long Bsd[BK][BN];          // 8 KB (dup pairs)

    const int tid = threadIdx.x;
    const int bm = blockIdx.y, bn = blockIdx.x;

    const float* Ab = A + (size_t)bm * BM * K;
    const float* Bb = B + (size_t)bn * BN;

    const int aRow = tid >> 1;            // 0..127
    const int aCol = (tid & 1) * 4;       // 0 or 4
    const int bRow = tid >> 5;            // 0..7
    const int bCol = (tid & 31) * 4;      // 0..124

    const int ty = tid >> 4;              // 0..15 (M sub-tile)
    const int tx = tid & 15;              // 0..15 (N sub-tile)

    unsigned long long acc[4][8];
#pragma unroll
    for (int i = 0; i < 4; i++)
#pragma unroll
        for (int j = 0; j < 8; j++) acc[i][j] = 0ull;

    for (int k0 = 0; k0 < K; k0 += BK) {
        float4 av = *(const float4*)(Ab + (size_t)aRow * K + k0 + aCol);
        As[aCol + 0][aRow] = av.x;
        As[aCol + 1][aRow] = av.y;
        As[aCol + 2][aRow] = av.z;
        As[aCol + 3][aRow] = av.w;

        float4 bv4 = *(const float4*)(Bb + (size_t)(k0 + bRow) * N + bCol);
        Bsd[bRow][bCol + 0] = pack2(bv4.x, bv4.x);
        Bsd[bRow][bCol + 1] = pack2(bv4.y, bv4.y);
        Bsd[bRow][bCol + 2] = pack2(bv4.z, bv4.z);
        Bsd[bRow][bCol + 3] = pack2(bv4.w, bv4.w);

        __syncthreads();

#pragma unroll
        for (int kk = 0; kk < BK; kk++) {
            // A pairs: (a0,a1)(a2,a3)(a4,a5)(a6,a7) — direct b64 loads
            ulonglong2 a01 = *(const ulonglong2*)(&As[kk][ty * 8 + 0]);
            ulonglong2 a23 = *(const ulonglong2*)(&As[kk][ty * 8 + 4]);
            unsigned long long ra[4];
            ra[0] = a01.x; ra[1] = a01.y; ra[2] = a23.x; ra[3] = a23.y;

            unsigned long long rb[8];
            ulonglong2 b0 = *(const ulonglong2*)(&Bsd[kk][tx * 8 + 0]);
            ulonglong2 b1 = *(const ulonglong2*)(&Bsd[kk][tx * 8 + 2]);
            ulonglong2 b2 = *(const ulonglong2*)(&Bsd[kk][tx * 8 + 4]);
            ulonglong2 b3 = *(const ulonglong2*)(&Bsd[kk][tx * 8 + 6]);
            rb[0]=b0.x; rb[1]=b0.y; rb[2]=b1.x; rb[3]=b1.y;
            rb[4]=b2.x; rb[5]=b2.y; rb[6]=b3.x; rb[7]=b3.y;

#pragma unroll
            for (int i = 0; i < 4; i++)
#pragma unroll
                for (int j = 0; j < 8; j++)
                    fma2(acc[i][j], ra[i], rb[j]);
        }
        __syncthreads();
    }

    // epilogue: unpack pairs, add bias, store
    const int colBase = bn * BN + tx * 8;
    float bvv[8];
#pragma unroll
    for (int j = 0; j < 8; j++) bvv[j] = bias[colBase + j];

#pragma unroll
    for (int ip = 0; ip < 4; ip++) {
        float lo[8], hi[8];
#pragma unroll
        for (int j = 0; j < 8; j++) unpack2(acc[ip][j], lo[j], hi[j]);

        int row0 = bm * BM + ty * 8 + 2 * ip;
        float4 o0, o1;
        o0.x = lo[0] + bvv[0]; o0.y = lo[1] + bvv[1];
        o0.z = lo[2] + bvv[2]; o0.w = lo[3] + bvv[3];
        o1.x = lo[4] + bvv[4]; o1.y = lo[5] + bvv[5];
        o1.z = lo[6] + bvv[6]; o1.w = lo[7] + bvv[7];
        *(float4*)(&C[(size_t)row0 * N + colBase + 0]) = o0;
        *(float4*)(&C[(size_t)row0 * N + colBase + 4]) = o1;

        float4 p0, p1;
        p0.x = hi[0] + bvv[0]; p0.y = hi[1] + bvv[1];
        p0.z = hi[2] + bvv[2]; p0.w = hi[3] + bvv[3];
        p1.x = hi[4] + bvv[4]; p1.y = hi[5] + bvv[5];
        p1.z = hi[6] + bvv[6]; p1.w = hi[7] + bvv[7];
        *(float4*)(&C[(size_t)(row0 + 1) * N + colBase + 0]) = p0;
        *(float4*)(&C[(size_t)(row0 + 1) * N + colBase + 4]) = p1;
    }
}

// ---------------- softmax over 16 contiguous elements per row -------------
__global__ void softmax16_kernel(float* __restrict__ a, int rows)
{
    int r = blockIdx.x * blockDim.x + threadIdx.x;
    if (r >= rows) return;
    float* p = a + (size_t)r * 16;
    float v[16];
    float m = -1e30f;
#pragma unroll
    for (int i = 0; i < 16; i++) { v[i] = p[i]; m = fmaxf(m, v[i]); }
    float s = 0.f;
#pragma unroll
    for (int i = 0; i < 16; i++) { v[i] = __expf(v[i] - m); s += v[i]; }
    float inv = 1.f / s;
#pragma unroll
    for (int i = 0; i < 16; i++) p[i] = v[i] * inv;
}

// ---------------- trilinear deformable sampling ----------------------------
__global__ __launch_bounds__(256) void sample_kernel(
    const float* __restrict__ rp,      // (NB, LQ, NLEV, 3)
    const int*   __restrict__ shapes,  // (NLEV, 3) = D,H,W
    const int*   __restrict__ starts)  // (NLEV,)
{
    const int q    = blockIdx.x;          // n*LQ + lq
    const int h    = threadIdx.x >> 5;
    const int lane = threadIdx.x & 31;

    __shared__ float s_rp[NLEV * 3];
    __shared__ int   s_dim[NLEV * 3];
    __shared__ int   s_start[NLEV];
    if (threadIdx.x < NLEV * 3) {
        s_rp[threadIdx.x]  = rp[(size_t)q * (NLEV * 3) + threadIdx.x];
        s_dim[threadIdx.x] = shapes[threadIdx.x];
    }
    if (threadIdx.x < NLEV) s_start[threadIdx.x] = starts[threadIdx.x];
    __syncthreads();

    const int n = q / LQ;
    const float* offq = g_off  + (size_t)q * (NHEADS * NLEV * NPTS * 3) + h * (NLEV * NPTS * 3);
    const float* attq = g_attn + (size_t)q * (NHEADS * NLEV * NPTS)     + h * (NLEV * NPTS);

    float acc = 0.f;

#pragma unroll
    for (int l = 0; l < NLEV; l++) {
        const int D = s_dim[l * 3 + 0];
        const int H = s_dim[l * 3 + 1];
        const int W = s_dim[l * 3 + 2];
        const float fD = (float)D, fH = (float)H, fW = (float)W;
        const float* vbase = g_value
            + ((size_t)(n * LEN_IN + s_start[l])) * DM + h * DHEAD + lane;
        const float rx = s_rp[l * 3 + 0];
        const float ry = s_rp[l * 3 + 1];
        const float rz = s_rp[l * 3 + 2];

#pragma unroll
        for (int p = 0; p < NPTS; p++) {
            const int o = l * NPTS + p;
            const float a  = attq[o];
            const float x = (rx + offq[o * 3 + 0] / fW) * fW - 0.5f;
            const float y = (ry + offq[o * 3 + 1] / fH) * fH - 0.5f;
            const float z = (rz + offq[o * 3 + 2] / fD) * fD - 0.5f;

            const float x0f = floorf(x), y0f = floorf(y), z0f = floorf(z);
            const int   x0 = (int)x0f,   y0 = (int)y0f,   z0 = (int)z0f;
            const float fx = x - x0f,    fy = y - y0f,    fz = z - z0f;

#pragma unroll
            for (int c = 0; c < 8; c++) {
                const int dx = c & 1, dy = (c >> 1) & 1, dz = (c >> 2) & 1;
                const int xi = x0 + dx, yi = y0 + dy, zi = z0 + dz;
                const float w = (dx ? fx : 1.f - fx)
                              * (dy ? fy : 1.f - fy)
                              * (dz ? fz : 1.f - fz);
                if (xi >= 0 && xi < W && yi >= 0 && yi < H &&
                    zi >= 0 && zi < D && w != 0.f) {
                    const size_t idx = ((size_t)zi * H + yi) * W + xi;
                    acc = fmaf(a * w, vbase[idx * DM], acc);
                }
            }
        }
    }

    g_mid[(size_t)q * DM + h * DHEAD + lane] = acc;
}

// ---------------------------------------------------------------------------
extern "C" void kernel_launch(void* const* d_in, const int* in_sizes, int n_in,
                              void* d_out, int out_size)
{
    const float* query  = (const float*)d_in[0];
    const float* refp   = (const float*)d_in[1];
    const float* inp    = (const float*)d_in[2];
    const int*   shapes = (const int*)  d_in[3];
    const int*   starts = (const int*)  d_in[4];
    const float* Wv     = (const float*)d_in[5];
    const float* bv     = (const float*)d_in[6];
    const float* Woff   = (const float*)d_in[7];
    const float* boff   = (const float*)d_in[8];
    const float* Wattn  = (const float*)d_in[9];
    const float* battn  = (const float*)d_in[10];
    const float* Wout   = (const float*)d_in[11];
    const float* bout   = (const float*)d_in[12];
    float* out = (float*)d_out;

    float *pv, *po, *pa, *pm;
    cudaGetSymbolAddress((void**)&pv, g_value);
    cudaGetSymbolAddress((void**)&po, g_off);
    cudaGetSymbolAddress((void**)&pa, g_attn);
    cudaGetSymbolAddress((void**)&pm, g_mid);

    dim3 blk(256);

    // 1) value = input_flatten @ Wv + bv      (299520 x 256 x 256)
    {
        dim3 grid(DM / 128, (NB * LEN_IN) / 128);
        sgemm_bias_kernel<<<grid, blk>>>(inp, Wv, bv, pv, NB * LEN_IN, DM, DM);
    }
    // 2) off = query @ Woff + boff            (16384 x 384 x 256)
    {
        dim3 grid(384 / 128, (NB * LQ) / 128);
        sgemm_bias_kernel<<<grid, blk>>>(query, Woff, boff, po, NB * LQ, 384, DM);
    }
    // 3) attn logits = query @ Wattn + battn  (16384 x 128 x 256)
    {
        dim3 grid(128 / 128, (NB * LQ) / 128);
        sgemm_bias_kernel<<<grid, blk>>>(query, Wattn, battn, pa, NB * LQ, 128, DM);
    }
    // 4) softmax over 16 (levels*points) per (n,q,head)
    softmax16_kernel<<<(NB * LQ * NHEADS + 255) / 256, 256>>>(pa, NB * LQ * NHEADS);

    // 5) deformable trilinear sampling -> g_mid
    sample_kernel<<<NB * LQ, 256>>>(refp, shapes, starts);

    // 6) out = g_mid @ Wout + bout            (16384 x 256 x 256)
    {
        dim3 grid(DM / 128, (NB * LQ) / 128);
        sgemm_bias_kernel<<<grid, blk>>>(pm, Wout, bout, out, NB * LQ, DM, DM);
    }
}

// round 4
// speedup vs baseline: 3.0233x; 3.0233x over previous
#include <cuda_runtime.h>
#include <cuda_bf16.h>
#include <math.h>
#include <stdint.h>

#define NB      2
#define LQ      8192
#define LEN_IN  149760
#define DM      256
#define NHEADS  8
#define NLEV    4
#define NPTS    4
#define DHEAD   32

// ---------------- scratch (device globals; no cudaMalloc allowed) ----------
__device__ float g_value[(size_t)NB * LEN_IN * DM];                      // 306 MB
__device__ float g_off  [(size_t)NB * LQ * (NHEADS * NLEV * NPTS * 3)]; // 25 MB
__device__ float g_attn [(size_t)NB * LQ * (NHEADS * NLEV * NPTS)];     // 8 MB
__device__ float g_mid  [(size_t)NB * LQ * DM];                         // 16 MB
__device__ __nv_bfloat16 g_wv_hi [DM * DM];   // Wv^T  hi split, [N][K]
__device__ __nv_bfloat16 g_wv_lo [DM * DM];
__device__ __nv_bfloat16 g_wo_hi [DM * DM];   // Wout^T hi split
__device__ __nv_bfloat16 g_wo_lo [DM * DM];

// ============================ PTX helpers ===================================
__device__ __forceinline__ uint32_t smem_u32(const void* p) {
    uint32_t a;
    asm("{ .reg .u64 t; cvta.to.shared.u64 t, %1; cvt.u32.u64 %0, t; }" : "=r"(a) : "l"(p));
    return a;
}
__device__ __forceinline__ void ldsm_x4(uint32_t* r, uint32_t addr) {
    asm volatile("ldmatrix.sync.aligned.m8n8.x4.shared.b16 {%0,%1,%2,%3}, [%4];"
        : "=r"(r[0]), "=r"(r[1]), "=r"(r[2]), "=r"(r[3]) : "r"(addr));
}
__device__ __forceinline__ void mma_bf16(float* d, const uint32_t* a,
                                         uint32_t b0, uint32_t b1) {
    asm volatile(
        "mma.sync.aligned.m16n8k16.row.col.f32.bf16.bf16.f32 "
        "{%0,%1,%2,%3}, {%4,%5,%6,%7}, {%8,%9}, {%0,%1,%2,%3};"
        : "+f"(d[0]), "+f"(d[1]), "+f"(d[2]), "+f"(d[3])
        : "r"(a[0]), "r"(a[1]), "r"(a[2]), "r"(a[3]), "r"(b0), "r"(b1));
}

// ======= mma.sync split-bf16 GEMM: C = A(Mx256) * B(256x256) + bias ========
// Grid: (2, M/128). 256 threads = 8 warps (2 m-warps x 4 n-warps).
// B pre-transposed + split to bf16 [N][K] in global (g_w*_hi/lo).
// A converted to (hi, lo) bf16 in-kernel. Products: hh + hl + lh.
// SMEM rows padded to 72 bf16 (144 B) -> 16B rotation/row, conflict-free
// ldmatrix phases. A_hi/A_lo/B_hi/B_lo each 128 x 72 bf16 = 18 KB.
#define SA        72
#define OFF_AHI   0
#define OFF_ALO   18432
#define OFF_BHI   36864
#define OFF_BLO   55296
#define SMEM_MMA  73728

__global__ __launch_bounds__(256, 1) void mma_gemm_kernel(
    const float* __restrict__ A,
    const __nv_bfloat16* __restrict__ Bt_hi,
    const __nv_bfloat16* __restrict__ Bt_lo,
    const float* __restrict__ bias,
    float* __restrict__ C)
{
    extern __shared__ char smem[];
    const uint32_t sb = smem_u32(smem);
    const int tid   = threadIdx.x;
    const int lane  = tid & 31;
    const int wid   = tid >> 5;
    const int mwarp = wid & 1;          // 0..1  (64 rows each)
    const int nwarp = wid >> 1;         // 0..3  (32 cols each)
    const int bn    = blockIdx.x;       // 0..1
    const size_t rowBase = (size_t)blockIdx.y * 128;

    float acc[4][4][4];
#pragma unroll
    for (int i = 0; i < 4; i++)
#pragma unroll
        for (int j = 0; j < 4; j++)
#pragma unroll
            for (int r = 0; r < 4; r++) acc[i][j][r] = 0.f;

    // ldmatrix source addresses (lane-dependent, k-step added in loop)
    const int a_row = lane & 15, a_kh = lane >> 4;
    const uint32_t aAddrHi = sb + OFF_AHI +
        (uint32_t)(((mwarp * 64 + a_row) * SA + a_kh * 8) * 2);
    const int b_g = lane >> 3, b_r = lane & 7;
    const uint32_t bAddrHi = sb + OFF_BHI +
        (uint32_t)(((nwarp * 32 + (b_g >> 1) * 8 + b_r) * SA + (b_g & 1) * 8) * 2);

#pragma unroll 1
    for (int ch = 0; ch < 4; ch++) {
        const int k0 = ch * 64;

        // ---- load A chunk 128x64 f32 -> hi/lo bf16 smem ----
#pragma unroll
        for (int it = 0; it < 8; it++) {
            int idx = tid + it * 256;            // 0..2047 float4 slots
            int row = idx >> 4, q = idx & 15;
            float4 v = *(const float4*)(A + (rowBase + row) * 256 + k0 + q * 4);
            __nv_bfloat162 h01 = __floats2bfloat162_rn(v.x, v.y);
            __nv_bfloat162 h23 = __floats2bfloat162_rn(v.z, v.w);
            float lx = v.x - __bfloat162float(__low2bfloat16(h01));
            float ly = v.y - __bfloat162float(__high2bfloat16(h01));
            float lz = v.z - __bfloat162float(__low2bfloat16(h23));
            float lw = v.w - __bfloat162float(__high2bfloat16(h23));
            __nv_bfloat162 l01 = __floats2bfloat162_rn(lx, ly);
            __nv_bfloat162 l23 = __floats2bfloat162_rn(lz, lw);
            uint32_t eoff = (uint32_t)((row * SA + q * 4) * 2);
            *(uint2*)(smem + OFF_AHI + eoff) = make_uint2(*(uint32_t*)&h01, *(uint32_t*)&h23);
            *(uint2*)(smem + OFF_ALO + eoff) = make_uint2(*(uint32_t*)&l01, *(uint32_t*)&l23);
        }
        // ---- load B chunk 128(n) x 64(k) bf16 hi/lo ----
#pragma unroll
        for (int it = 0; it < 4; it++) {
            int idx = tid + it * 256;            // 0..1023 uint4 slots
            int n = idx >> 3, q = idx & 7;
            uint32_t eoff = (uint32_t)((n * SA + q * 8) * 2);
            size_t goff = (size_t)(bn * 128 + n) * 256 + k0 + q * 8;
            *(uint4*)(smem + OFF_BHI + eoff) = *(const uint4*)(Bt_hi + goff);
            *(uint4*)(smem + OFF_BLO + eoff) = *(const uint4*)(Bt_lo + goff);
        }
        __syncthreads();

#pragma unroll
        for (int ks = 0; ks < 4; ks++) {
            const uint32_t kb = (uint32_t)(ks * 32);   // 16 elems * 2B
            uint32_t ah[4][4], al[4][4];
#pragma unroll
            for (int mt = 0; mt < 4; mt++) {
                uint32_t ad = aAddrHi + (uint32_t)(mt * 16 * SA * 2) + kb;
                ldsm_x4(ah[mt], ad);
                ldsm_x4(al[mt], ad + (OFF_ALO - OFF_AHI));
            }
            uint32_t bh[2][4], bl[2][4];
#pragma unroll
            for (int pr = 0; pr < 2; pr++) {
                uint32_t bd = bAddrHi + (uint32_t)(pr * 16 * SA * 2) + kb;
                ldsm_x4(bh[pr], bd);
                ldsm_x4(bl[pr], bd + (OFF_BLO - OFF_BHI));
            }
#pragma unroll
            for (int mt = 0; mt < 4; mt++)
#pragma unroll
                for (int nt = 0; nt < 4; nt++) {
                    const int pr = nt >> 1, h = (nt & 1) * 2;
                    mma_bf16(acc[mt][nt], ah[mt], bh[pr][h], bh[pr][h + 1]);
                    mma_bf16(acc[mt][nt], ah[mt], bl[pr][h], bl[pr][h + 1]);
                    mma_bf16(acc[mt][nt], al[mt], bh[pr][h], bh[pr][h + 1]);
                }
        }
        __syncthreads();
    }

    // ---- epilogue: add bias, store float2s ----
#pragma unroll
    for (int nt = 0; nt < 4; nt++) {
        const int col = bn * 128 + nwarp * 32 + nt * 8 + (lane & 3) * 2;
        const float2 bb = *(const float2*)(bias + col);
#pragma unroll
        for (int mt = 0; mt < 4; mt++) {
            const size_t row0 = rowBase + mwarp * 64 + mt * 16 + (lane >> 2);
            float2 o0, o1;
            o0.x = acc[mt][nt][0] + bb.x; o0.y = acc[mt][nt][1] + bb.y;
            o1.x = acc[mt][nt][2] + bb.x; o1.y = acc[mt][nt][3] + bb.y;
            *(float2*)(C + row0 * 256 + col)        = o0;
            *(float2*)(C + (row0 + 8) * 256 + col)  = o1;
        }
    }
}

// ---- prep: W (K x N row-major f32) -> transposed split bf16 [N][K] --------
__global__ void prep_b_kernel(const float* __restrict__ W,
                              __nv_bfloat16* __restrict__ bhi,
                              __nv_bfloat16* __restrict__ blo)
{
    int idx = blockIdx.x * 256 + threadIdx.x;   // 0..65535
    int n = idx >> 8, k = idx & 255;
    float v = W[k * 256 + n];
    __nv_bfloat16 h = __float2bfloat16(v);
    bhi[idx] = h;
    blo[idx] = __float2bfloat16(v - __bfloat162float(h));
}

// ---------------- fp32 FFMA GEMM for the small GEMMs -----------------------
__global__ __launch_bounds__(256) void sgemm_bias_kernel(
    const float* __restrict__ A, const float* __restrict__ B,
    const float* __restrict__ bias, float* __restrict__ C,
    int M, int N, int K)
{
    const int BM = 128, BN = 128, BK = 8;
    __shared__ float As[BK][BM];
    __shared__ float Bs[BK][BN];

    const int tid = threadIdx.x;
    const int bm = blockIdx.y, bn = blockIdx.x;
    const float* Ab = A + (size_t)bm * BM * K;
    const float* Bb = B + (size_t)bn * BN;
    const int aRow = tid >> 1, aCol = (tid & 1) * 4;
    const int bRow = tid >> 5, bCol = (tid & 31) * 4;
    const int ty = tid >> 4, tx = tid & 15;

    float acc[8][8];
#pragma unroll
    for (int i = 0; i < 8; i++)
#pragma unroll
        for (int j = 0; j < 8; j++) acc[i][j] = 0.f;

    for (int k0 = 0; k0 < K; k0 += BK) {
        float4 av = *(const float4*)(Ab + (size_t)aRow * K + k0 + aCol);
        As[aCol + 0][aRow] = av.x;
        As[aCol + 1][aRow] = av.y;
        As[aCol + 2][aRow] = av.z;
        As[aCol + 3][aRow] = av.w;
        float4 bv4 = *(const float4*)(Bb + (size_t)(k0 + bRow) * N + bCol);
        *(float4*)(&Bs[bRow][bCol]) = bv4;
        __syncthreads();
#pragma unroll
        for (int kk = 0; kk < BK; kk++) {
            float regA[8], regB[8];
            float4 a0 = *(const float4*)(&As[kk][ty * 8 + 0]);
            float4 a1 = *(const float4*)(&As[kk][ty * 8 + 4]);
            regA[0]=a0.x; regA[1]=a0.y; regA[2]=a0.z; regA[3]=a0.w;
            regA[4]=a1.x; regA[5]=a1.y; regA[6]=a1.z; regA[7]=a1.w;
            float4 b0 = *(const float4*)(&Bs[kk][tx * 8 + 0]);
            float4 b1 = *(const float4*)(&Bs[kk][tx * 8 + 4]);
            regB[0]=b0.x; regB[1]=b0.y; regB[2]=b0.z; regB[3]=b0.w;
            regB[4]=b1.x; regB[5]=b1.y; regB[6]=b1.z; regB[7]=b1.w;
#pragma unroll
            for (int i = 0; i < 8; i++)
#pragma unroll
                for (int j = 0; j < 8; j++)
                    acc[i][j] = fmaf(regA[i], regB[j], acc[i][j]);
        }
        __syncthreads();
    }

    const int colBase = bn * BN + tx * 8;
    float bvv[8];
#pragma unroll
    for (int j = 0; j < 8; j++) bvv[j] = bias[colBase + j];
#pragma unroll
    for (int i = 0; i < 8; i++) {
        int row = bm * BM + ty * 8 + i;
        float4 o0, o1;
        o0.x = acc[i][0] + bvv[0]; o0.y = acc[i][1] + bvv[1];
        o0.z = acc[i][2] + bvv[2]; o0.w = acc[i][3] + bvv[3];
        o1.x = acc[i][4] + bvv[4]; o1.y = acc[i][5] + bvv[5];
        o1.z = acc[i][6] + bvv[6]; o1.w = acc[i][7] + bvv[7];
        *(float4*)(&C[(size_t)row * N + colBase + 0]) = o0;
        *(float4*)(&C[(size_t)row * N + colBase + 4]) = o1;
    }
}

// ---------------- softmax over 16 contiguous elements per row -------------
__global__ void softmax16_kernel(float* __restrict__ a, int rows)
{
    int r = blockIdx.x * blockDim.x + threadIdx.x;
    if (r >= rows) return;
    float* p = a + (size_t)r * 16;
    float v[16];
    float m = -1e30f;
#pragma unroll
    for (int i = 0; i < 16; i++) { v[i] = p[i]; m = fmaxf(m, v[i]); }
    float s = 0.f;
#pragma unroll
    for (int i = 0; i < 16; i++) { v[i] = __expf(v[i] - m); s += v[i]; }
    float inv = 1.f / s;
#pragma unroll
    for (int i = 0; i < 16; i++) p[i] = v[i] * inv;
}

// ---------------- trilinear deformable sampling ----------------------------
__global__ __launch_bounds__(256) void sample_kernel(
    const float* __restrict__ rp,
    const int*   __restrict__ shapes,
    const int*   __restrict__ starts)
{
    const int q    = blockIdx.x;
    const int h    = threadIdx.x >> 5;
    const int lane = threadIdx.x & 31;

    __shared__ float s_rp[NLEV * 3];
    __shared__ int   s_dim[NLEV * 3];
    __shared__ int   s_start[NLEV];
    if (threadIdx.x < NLEV * 3) {
        s_rp[threadIdx.x]  = rp[(size_t)q * (NLEV * 3) + threadIdx.x];
        s_dim[threadIdx.x] = shapes[threadIdx.x];
    }
    if (threadIdx.x < NLEV) s_start[threadIdx.x] = starts[threadIdx.x];
    __syncthreads();

    const int n = q / LQ;
    const float* offq = g_off  + (size_t)q * (NHEADS * NLEV * NPTS * 3) + h * (NLEV * NPTS * 3);
    const float* attq = g_attn + (size_t)q * (NHEADS * NLEV * NPTS)     + h * (NLEV * NPTS);

    float acc = 0.f;
#pragma unroll
    for (int l = 0; l < NLEV; l++) {
        const int D = s_dim[l * 3 + 0];
        const int H = s_dim[l * 3 + 1];
        const int W = s_dim[l * 3 + 2];
        const float fD = (float)D, fH = (float)H, fW = (float)W;
        const float* vbase = g_value
            + ((size_t)(n * LEN_IN + s_start[l])) * DM + h * DHEAD + lane;
        const float rx = s_rp[l * 3 + 0];
        const float ry = s_rp[l * 3 + 1];
        const float rz = s_rp[l * 3 + 2];
#pragma unroll
        for (int p = 0; p < NPTS; p++) {
            const int o = l * NPTS + p;
            const float a  = attq[o];
            const float x = (rx + offq[o * 3 + 0] / fW) * fW - 0.5f;
            const float y = (ry + offq[o * 3 + 1] / fH) * fH - 0.5f;
            const float z = (rz + offq[o * 3 + 2] / fD) * fD - 0.5f;
            const float x0f = floorf(x), y0f = floorf(y), z0f = floorf(z);
            const int   x0 = (int)x0f,   y0 = (int)y0f,   z0 = (int)z0f;
            const float fx = x - x0f,    fy = y - y0f,    fz = z - z0f;
#pragma unroll
            for (int c = 0; c < 8; c++) {
                const int dx = c & 1, dy = (c >> 1) & 1, dz = (c >> 2) & 1;
                const int xi = x0 + dx, yi = y0 + dy, zi = z0 + dz;
                const float w = (dx ? fx : 1.f - fx)
                              * (dy ? fy : 1.f - fy)
                              * (dz ? fz : 1.f - fz);
                if (xi >= 0 && xi < W && yi >= 0 && yi < H &&
                    zi >= 0 && zi < D && w != 0.f) {
                    const size_t idx = ((size_t)zi * H + yi) * W + xi;
                    acc = fmaf(a * w, vbase[idx * DM], acc);
                }
            }
        }
    }
    g_mid[(size_t)q * DM + h * DHEAD + lane] = acc;
}

// ---------------------------------------------------------------------------
extern "C" void kernel_launch(void* const* d_in, const int* in_sizes, int n_in,
                              void* d_out, int out_size)
{
    const float* query  = (const float*)d_in[0];
    const float* refp   = (const float*)d_in[1];
    const float* inp    = (const float*)d_in[2];
    const int*   shapes = (const int*)  d_in[3];
    const int*   starts = (const int*)  d_in[4];
    const float* Wv     = (const float*)d_in[5];
    const float* bv     = (const float*)d_in[6];
    const float* Woff   = (const float*)d_in[7];
    const float* boff   = (const float*)d_in[8];
    const float* Wattn  = (const float*)d_in[9];
    const float* battn  = (const float*)d_in[10];
    const float* Wout   = (const float*)d_in[11];
    const float* bout   = (const float*)d_in[12];
    float* out = (float*)d_out;

    float *pv, *po, *pa, *pm;
    __nv_bfloat16 *pwvh, *pwvl, *pwoh, *pwol;
    cudaGetSymbolAddress((void**)&pv, g_value);
    cudaGetSymbolAddress((void**)&po, g_off);
    cudaGetSymbolAddress((void**)&pa, g_attn);
    cudaGetSymbolAddress((void**)&pm, g_mid);
    cudaGetSymbolAddress((void**)&pwvh, g_wv_hi);
    cudaGetSymbolAddress((void**)&pwvl, g_wv_lo);
    cudaGetSymbolAddress((void**)&pwoh, g_wo_hi);
    cudaGetSymbolAddress((void**)&pwol, g_wo_lo);

    cudaFuncSetAttribute(mma_gemm_kernel,
                         cudaFuncAttributeMaxDynamicSharedMemorySize, SMEM_MMA);

    // 0) prep transposed bf16 splits of Wv, Wout
    prep_b_kernel<<<256, 256>>>(Wv, pwvh, pwvl);
    prep_b_kernel<<<256, 256>>>(Wout, pwoh, pwol);

    // 1) value = input_flatten @ Wv + bv   (mma.sync, 299520 x 256 x 256)
    {
        dim3 grid(2, (NB * LEN_IN) / 128);
        mma_gemm_kernel<<<grid, 256, SMEM_MMA>>>(inp, pwvh, pwvl, bv, pv);
    }
    // 2) off = query @ Woff + boff         (16384 x 384 x 256, FFMA)
    {
        dim3 grid(384 / 128, (NB * LQ) / 128);
        sgemm_bias_kernel<<<grid, 256>>>(query, Woff, boff, po, NB * LQ, 384, DM);
    }
    // 3) attn logits = query @ Wattn + battn (16384 x 128 x 256, FFMA)
    {
        dim3 grid(1, (NB * LQ) / 128);
        sgemm_bias_kernel<<<grid, 256>>>(query, Wattn, battn, pa, NB * LQ, 128, DM);
    }
    // 4) softmax over 16
    softmax16_kernel<<<(NB * LQ * NHEADS + 255) / 256, 256>>>(pa, NB * LQ * NHEADS);

    // 5) deformable trilinear sampling -> g_mid
    sample_kernel<<<NB * LQ, 256>>>(refp, shapes, starts);

    // 6) out = g_mid @ Wout + bout          (mma.sync, 16384 x 256 x 256)
    {
        dim3 grid(2, (NB * LQ) / 128);
        mma_gemm_kernel<<<grid, 256, SMEM_MMA>>>(pm, pwoh, pwol, bout, out);
    }
}

// round 5
// speedup vs baseline: 3.3377x; 1.1040x over previous
#include <cuda_runtime.h>
#include <cuda_bf16.h>
#include <math.h>
#include <stdint.h>

#define NB      2
#define LQ      8192
#define LEN_IN  149760
#define DM      256
#define NHEADS  8
#define NLEV    4
#define NPTS    4
#define DHEAD   32

// ---------------- scratch (device globals; no cudaMalloc allowed) ----------
__device__ float g_value[(size_t)NB * LEN_IN * DM];                      // 306 MB
__device__ float g_off  [(size_t)NB * LQ * (NHEADS * NLEV * NPTS * 3)]; // 25 MB
__device__ float g_attn [(size_t)NB * LQ * (NHEADS * NLEV * NPTS)];     // 8 MB
__device__ float g_mid  [(size_t)NB * LQ * DM];                         // 16 MB
__device__ __nv_bfloat16 g_wv_hi [DM * DM];        // Wv^T    [N][K]
__device__ __nv_bfloat16 g_wv_lo [DM * DM];
__device__ __nv_bfloat16 g_wo_hi [DM * DM];        // Wout^T
__device__ __nv_bfloat16 g_wo_lo [DM * DM];
__device__ __nv_bfloat16 g_wf_hi [384 * DM];       // Woff^T  [384][256]
__device__ __nv_bfloat16 g_wf_lo [384 * DM];
__device__ __nv_bfloat16 g_wa_hi [128 * DM];       // Wattn^T [128][256]
__device__ __nv_bfloat16 g_wa_lo [128 * DM];

// ============================ PTX helpers ===================================
__device__ __forceinline__ uint32_t smem_u32(const void* p) {
    uint32_t a;
    asm("{ .reg .u64 t; cvta.to.shared.u64 t, %1; cvt.u32.u64 %0, t; }" : "=r"(a) : "l"(p));
    return a;
}
__device__ __forceinline__ void ldsm_x4(uint32_t* r, uint32_t addr) {
    asm volatile("ldmatrix.sync.aligned.m8n8.x4.shared.b16 {%0,%1,%2,%3}, [%4];"
        : "=r"(r[0]), "=r"(r[1]), "=r"(r[2]), "=r"(r[3]) : "r"(addr));
}
__device__ __forceinline__ void mma_bf16(float* d, const uint32_t* a,
                                         uint32_t b0, uint32_t b1) {
    asm volatile(
        "mma.sync.aligned.m16n8k16.row.col.f32.bf16.bf16.f32 "
        "{%0,%1,%2,%3}, {%4,%5,%6,%7}, {%8,%9}, {%0,%1,%2,%3};"
        : "+f"(d[0]), "+f"(d[1]), "+f"(d[2]), "+f"(d[3])
        : "r"(a[0]), "r"(a[1]), "r"(a[2]), "r"(a[3]), "r"(b0), "r"(b1));
}

// A fp32 -> (hi,lo) bf16 conversion of a float4, store to smem (uint2 each)
__device__ __forceinline__ void cvt_split_store(char* smem, int offHi, int offLo,
                                                uint32_t eoff, float4 v) {
    __nv_bfloat162 h01 = __floats2bfloat162_rn(v.x, v.y);
    __nv_bfloat162 h23 = __floats2bfloat162_rn(v.z, v.w);
    float lx = v.x - __bfloat162float(__low2bfloat16(h01));
    float ly = v.y - __bfloat162float(__high2bfloat16(h01));
    float lz = v.z - __bfloat162float(__low2bfloat16(h23));
    float lw = v.w - __bfloat162float(__high2bfloat16(h23));
    __nv_bfloat162 l01 = __floats2bfloat162_rn(lx, ly);
    __nv_bfloat162 l23 = __floats2bfloat162_rn(lz, lw);
    *(uint2*)(smem + offHi + eoff) = make_uint2(*(uint32_t*)&h01, *(uint32_t*)&h23);
    *(uint2*)(smem + offLo + eoff) = make_uint2(*(uint32_t*)&l01, *(uint32_t*)&l23);
}

// SMEM rows padded to 72 bf16 (144 B) -> conflict-free ldmatrix phases.
#define SA        72

// ---------------- generic 128x128-tile mma GEMM (off/attn/out) -------------
// Grid (Nc/128, M/128). B pre-transposed+split [Nc][256]. C stride = Nc.
#define OFF_AHI   0
#define OFF_ALO   18432
#define OFF_BHI   36864
#define OFF_BLO   55296
#define SMEM_MMA  73728

__global__ __launch_bounds__(256, 1) void mma_gemm_kernel(
    const float* __restrict__ A,
    const __nv_bfloat16* __restrict__ Bt_hi,
    const __nv_bfloat16* __restrict__ Bt_lo,
    const float* __restrict__ bias,
    float* __restrict__ C, int Nc)
{
    extern __shared__ char smem[];
    const uint32_t sb = smem_u32(smem);
    const int tid   = threadIdx.x;
    const int lane  = tid & 31;
    const int wid   = tid >> 5;
    const int mwarp = wid & 1;
    const int nwarp = wid >> 1;
    const int bn    = blockIdx.x;
    const size_t rowBase = (size_t)blockIdx.y * 128;

    float acc[4][4][4];
#pragma unroll
    for (int i = 0; i < 4; i++)
#pragma unroll
        for (int j = 0; j < 4; j++)
#pragma unroll
            for (int r = 0; r < 4; r++) acc[i][j][r] = 0.f;

    const int a_row = lane & 15, a_kh = lane >> 4;
    const uint32_t aAddrHi = sb + OFF_AHI +
        (uint32_t)(((mwarp * 64 + a_row) * SA + a_kh * 8) * 2);
    const int b_g = lane >> 3, b_r = lane & 7;
    const uint32_t bAddrHi = sb + OFF_BHI +
        (uint32_t)(((nwarp * 32 + (b_g >> 1) * 8 + b_r) * SA + (b_g & 1) * 8) * 2);

#pragma unroll 1
    for (int ch = 0; ch < 4; ch++) {
        const int k0 = ch * 64;
#pragma unroll
        for (int it = 0; it < 8; it++) {
            int idx = tid + it * 256;
            int row = idx >> 4, q = idx & 15;
            float4 v = *(const float4*)(A + (rowBase + row) * 256 + k0 + q * 4);
            cvt_split_store(smem, OFF_AHI, OFF_ALO,
                            (uint32_t)((row * SA + q * 4) * 2), v);
        }
#pragma unroll
        for (int it = 0; it < 4; it++) {
            int idx = tid + it * 256;
            int n = idx >> 3, q = idx & 7;
            uint32_t eoff = (uint32_t)((n * SA + q * 8) * 2);
            size_t goff = (size_t)(bn * 128 + n) * 256 + k0 + q * 8;
            *(uint4*)(smem + OFF_BHI + eoff) = *(const uint4*)(Bt_hi + goff);
            *(uint4*)(smem + OFF_BLO + eoff) = *(const uint4*)(Bt_lo + goff);
        }
        __syncthreads();

#pragma unroll
        for (int ks = 0; ks < 4; ks++) {
            const uint32_t kb = (uint32_t)(ks * 32);
            uint32_t ah[4][4], al[4][4];
#pragma unroll
            for (int mt = 0; mt < 4; mt++) {
                uint32_t ad = aAddrHi + (uint32_t)(mt * 16 * SA * 2) + kb;
                ldsm_x4(ah[mt], ad);
                ldsm_x4(al[mt], ad + (OFF_ALO - OFF_AHI));
            }
            uint32_t bh[2][4], bl[2][4];
#pragma unroll
            for (int pr = 0; pr < 2; pr++) {
                uint32_t bd = bAddrHi + (uint32_t)(pr * 16 * SA * 2) + kb;
                ldsm_x4(bh[pr], bd);
                ldsm_x4(bl[pr], bd + (OFF_BLO - OFF_BHI));
            }
#pragma unroll
            for (int mt = 0; mt < 4; mt++)
#pragma unroll
                for (int nt = 0; nt < 4; nt++) {
                    const int pr = nt >> 1, h = (nt & 1) * 2;
                    mma_bf16(acc[mt][nt], ah[mt], bh[pr][h], bh[pr][h + 1]);
                    mma_bf16(acc[mt][nt], ah[mt], bl[pr][h], bl[pr][h + 1]);
                    mma_bf16(acc[mt][nt], al[mt], bh[pr][h], bh[pr][h + 1]);
                }
        }
        __syncthreads();
    }

#pragma unroll
    for (int nt = 0; nt < 4; nt++) {
        const int col = bn * 128 + nwarp * 32 + nt * 8 + (lane & 3) * 2;
        const float2 bb = *(const float2*)(bias + col);
#pragma unroll
        for (int mt = 0; mt < 4; mt++) {
            const size_t row0 = rowBase + mwarp * 64 + mt * 16 + (lane >> 2);
            float2 o0, o1;
            o0.x = acc[mt][nt][0] + bb.x; o0.y = acc[mt][nt][1] + bb.y;
            o1.x = acc[mt][nt][2] + bb.x; o1.y = acc[mt][nt][3] + bb.y;
            *(float2*)(C + row0 * Nc + col)       = o0;
            *(float2*)(C + (row0 + 8) * Nc + col) = o1;
        }
    }
}

// ---------------- 128x256-tile mma GEMM (value / out projections) ----------
// Grid (M/128). Full N=256 per CTA -> A loaded/converted once.
#define V_AHI   0
#define V_ALO   18432
#define V_BHI   36864
#define V_BLO   73728
#define SMEM_V  110592

__global__ __launch_bounds__(256, 1) void mma_gemm256_kernel(
    const float* __restrict__ A,
    const __nv_bfloat16* __restrict__ Bt_hi,
    const __nv_bfloat16* __restrict__ Bt_lo,
    const float* __restrict__ bias,
    float* __restrict__ C)
{
    extern __shared__ char smem[];
    const uint32_t sb = smem_u32(smem);
    const int tid   = threadIdx.x;
    const int lane  = tid & 31;
    const int wid   = tid >> 5;
    const int mwarp = wid & 1;          // 64 rows each
    const int nwarp = wid >> 1;         // 64 cols each
    const size_t rowBase = (size_t)blockIdx.x * 128;

    float acc[4][8][4];
#pragma unroll
    for (int i = 0; i < 4; i++)
#pragma unroll
        for (int j = 0; j < 8; j++)
#pragma unroll
            for (int r = 0; r < 4; r++) acc[i][j][r] = 0.f;

    const int a_row = lane & 15, a_kh = lane >> 4;
    const uint32_t aAddrHi = sb + V_AHI +
        (uint32_t)(((mwarp * 64 + a_row) * SA + a_kh * 8) * 2);
    const int b_g = lane >> 3, b_r = lane & 7;
    const uint32_t bAddrHi = sb + V_BHI +
        (uint32_t)(((nwarp * 64 + (b_g >> 1) * 8 + b_r) * SA + (b_g & 1) * 8) * 2);

#pragma unroll 1
    for (int ch = 0; ch < 4; ch++) {
        const int k0 = ch * 64;
        // A chunk 128x64 -> split bf16
#pragma unroll
        for (int it = 0; it < 8; it++) {
            int idx = tid + it * 256;
            int row = idx >> 4, q = idx & 15;
            float4 v = *(const float4*)(A + (rowBase + row) * 256 + k0 + q * 4);
            cvt_split_store(smem, V_AHI, V_ALO,
                            (uint32_t)((row * SA + q * 4) * 2), v);
        }
        // B chunk 256(n) x 64(k) hi/lo
#pragma unroll
        for (int it = 0; it < 8; it++) {
            int idx = tid + it * 256;            // 0..2047 uint4 slots
            int n = idx >> 3, q = idx & 7;
            uint32_t eoff = (uint32_t)((n * SA + q * 8) * 2);
            size_t goff = (size_t)n * 256 + k0 + q * 8;
            *(uint4*)(smem + V_BHI + eoff) = *(const uint4*)(Bt_hi + goff);
            *(uint4*)(smem + V_BLO + eoff) = *(const uint4*)(Bt_lo + goff);
        }
        __syncthreads();

#pragma unroll
        for (int ks = 0; ks < 4; ks++) {
            const uint32_t kb = (uint32_t)(ks * 32);
            uint32_t ah[4][4], al[4][4];
#pragma unroll
            for (int mt = 0; mt < 4; mt++) {
                uint32_t ad = aAddrHi + (uint32_t)(mt * 16 * SA * 2) + kb;
                ldsm_x4(ah[mt], ad);
                ldsm_x4(al[mt], ad + (V_ALO - V_AHI));
            }
#pragma unroll
            for (int pr = 0; pr < 4; pr++) {
                uint32_t bh[4], bl[4];
                uint32_t bd = bAddrHi + (uint32_t)(pr * 16 * SA * 2) + kb;
                ldsm_x4(bh, bd);
                ldsm_x4(bl, bd + (V_BLO - V_BHI));
#pragma unroll
                for (int h2 = 0; h2 < 2; h2++) {
                    const int nt = pr * 2 + h2, h = h2 * 2;
#pragma unroll
                    for (int mt = 0; mt < 4; mt++) {
                        mma_bf16(acc[mt][nt], ah[mt], bh[h], bh[h + 1]);
                        mma_bf16(acc[mt][nt], ah[mt], bl[h], bl[h + 1]);
                        mma_bf16(acc[mt][nt], al[mt], bh[h], bh[h + 1]);
                    }
                }
            }
        }
        __syncthreads();
    }

#pragma unroll
    for (int nt = 0; nt < 8; nt++) {
        const int col = nwarp * 64 + nt * 8 + (lane & 3) * 2;
        const float2 bb = *(const float2*)(bias + col);
#pragma unroll
        for (int mt = 0; mt < 4; mt++) {
            const size_t row0 = rowBase + mwarp * 64 + mt * 16 + (lane >> 2);
            float2 o0, o1;
            o0.x = acc[mt][nt][0] + bb.x; o0.y = acc[mt][nt][1] + bb.y;
            o1.x = acc[mt][nt][2] + bb.x; o1.y = acc[mt][nt][3] + bb.y;
            *(float2*)(C + row0 * 256 + col)       = o0;
            *(float2*)(C + (row0 + 8) * 256 + col) = o1;
        }
    }
}

// ---- prep: W (256 x N row-major f32) -> transposed split bf16 [N][256] ----
__global__ void prep_b_kernel(const float* __restrict__ W,
                              __nv_bfloat16* __restrict__ bhi,
                              __nv_bfloat16* __restrict__ blo, int N)
{
    int idx = blockIdx.x * 256 + threadIdx.x;
    if (idx >= N * 256) return;
    int n = idx >> 8, k = idx & 255;
    float v = W[k * N + n];
    __nv_bfloat16 h = __float2bfloat16(v);
    bhi[idx] = h;
    blo[idx] = __float2bfloat16(v - __bfloat162float(h));
}

// ---------------- softmax over 16 contiguous elements per row -------------
__global__ void softmax16_kernel(float* __restrict__ a, int rows)
{
    int r = blockIdx.x * blockDim.x + threadIdx.x;
    if (r >= rows) return;
    float* p = a + (size_t)r * 16;
    float v[16];
    float m = -1e30f;
#pragma unroll
    for (int i = 0; i < 16; i++) { v[i] = p[i]; m = fmaxf(m, v[i]); }
    float s = 0.f;
#pragma unroll
    for (int i = 0; i < 16; i++) { v[i] = __expf(v[i] - m); s += v[i]; }
    float inv = 1.f / s;
#pragma unroll
    for (int i = 0; i < 16; i++) p[i] = v[i] * inv;
}

// ---------------- trilinear deformable sampling ----------------------------
__global__ __launch_bounds__(256) void sample_kernel(
    const float* __restrict__ rp,
    const int*   __restrict__ shapes,
    const int*   __restrict__ starts)
{
    const int q    = blockIdx.x;
    const int h    = threadIdx.x >> 5;
    const int lane = threadIdx.x & 31;

    __shared__ float s_rp[NLEV * 3];
    __shared__ int   s_dim[NLEV * 3];
    __shared__ int   s_start[NLEV];
    if (threadIdx.x < NLEV * 3) {
        s_rp[threadIdx.x]  = rp[(size_t)q * (NLEV * 3) + threadIdx.x];
        s_dim[threadIdx.x] = shapes[threadIdx.x];
    }
    if (threadIdx.x < NLEV) s_start[threadIdx.x] = starts[threadIdx.x];
    __syncthreads();

    const int n = q / LQ;
    const float* offq = g_off  + (size_t)q * (NHEADS * NLEV * NPTS * 3) + h * (NLEV * NPTS * 3);
    const float* attq = g_attn + (size_t)q * (NHEADS * NLEV * NPTS)     + h * (NLEV * NPTS);

    float acc0 = 0.f, acc1 = 0.f;
#pragma unroll
    for (int l = 0; l < NLEV; l++) {
        const int D = s_dim[l * 3 + 0];
        const int H = s_dim[l * 3 + 1];
        const int W = s_dim[l * 3 + 2];
        const float fD = (float)D, fH = (float)H, fW = (float)W;
        const float* vbase = g_value
            + ((size_t)(n * LEN_IN + s_start[l])) * DM + h * DHEAD + lane;
        const float rx = s_rp[l * 3 + 0];
        const float ry = s_rp[l * 3 + 1];
        const float rz = s_rp[l * 3 + 2];
#pragma unroll
        for (int p = 0; p < NPTS; p++) {
            const int o = l * NPTS + p;
            const float a  = attq[o];
            const float x = (rx + offq[o * 3 + 0] / fW) * fW - 0.5f;
            const float y = (ry + offq[o * 3 + 1] / fH) * fH - 0.5f;
            const float z = (rz + offq[o * 3 + 2] / fD) * fD - 0.5f;
            const float x0f = floorf(x), y0f = floorf(y), z0f = floorf(z);
            const int   x0 = (int)x0f,   y0 = (int)y0f,   z0 = (int)z0f;
            const float fx = x - x0f,    fy = y - y0f,    fz = z - z0f;
#pragma unroll
            for (int c = 0; c < 8; c++) {
                const int dx = c & 1, dy = (c >> 1) & 1, dz = (c >> 2) & 1;
                const int xi = x0 + dx, yi = y0 + dy, zi = z0 + dz;
                const float w = (dx ? fx : 1.f - fx)
                              * (dy ? fy : 1.f - fy)
                              * (dz ? fz : 1.f - fz);
                if (xi >= 0 && xi < W && yi >= 0 && yi < H &&
                    zi >= 0 && zi < D && w != 0.f) {
                    const size_t idx = ((size_t)zi * H + yi) * W + xi;
                    const float vv = __ldg(vbase + idx * DM);
                    if (c & 1) acc1 = fmaf(a * w, vv, acc1);
                    else       acc0 = fmaf(a * w, vv, acc0);
                }
            }
        }
    }
    g_mid[(size_t)q * DM + h * DHEAD + lane] = acc0 + acc1;
}

// ---------------------------------------------------------------------------
extern "C" void kernel_launch(void* const* d_in, const int* in_sizes, int n_in,
                              void* d_out, int out_size)
{
    const float* query  = (const float*)d_in[0];
    const float* refp   = (const float*)d_in[1];
    const float* inp    = (const float*)d_in[2];
    const int*   shapes = (const int*)  d_in[3];
    const int*   starts = (const int*)  d_in[4];
    const float* Wv     = (const float*)d_in[5];
    const float* bv     = (const float*)d_in[6];
    const float* Woff   = (const float*)d_in[7];
    const float* boff   = (const float*)d_in[8];
    const float* Wattn  = (const float*)d_in[9];
    const float* battn  = (const float*)d_in[10];
    const float* Wout   = (const float*)d_in[11];
    const float* bout   = (const float*)d_in[12];
    float* out = (float*)d_out;

    float *pv, *po, *pa, *pm;
    __nv_bfloat16 *pwvh, *pwvl, *pwoh, *pwol, *pwfh, *pwfl, *pwah, *pwal;
    cudaGetSymbolAddress((void**)&pv, g_value);
    cudaGetSymbolAddress((void**)&po, g_off);
    cudaGetSymbolAddress((void**)&pa, g_attn);
    cudaGetSymbolAddress((void**)&pm, g_mid);
    cudaGetSymbolAddress((void**)&pwvh, g_wv_hi);
    cudaGetSymbolAddress((void**)&pwvl, g_wv_lo);
    cudaGetSymbolAddress((void**)&pwoh, g_wo_hi);
    cudaGetSymbolAddress((void**)&pwol, g_wo_lo);
    cudaGetSymbolAddress((void**)&pwfh, g_wf_hi);
    cudaGetSymbolAddress((void**)&pwfl, g_wf_lo);
    cudaGetSymbolAddress((void**)&pwah, g_wa_hi);
    cudaGetSymbolAddress((void**)&pwal, g_wa_lo);

    cudaFuncSetAttribute(mma_gemm_kernel,
                         cudaFuncAttributeMaxDynamicSharedMemorySize, SMEM_MMA);
    cudaFuncSetAttribute(mma_gemm256_kernel,
                         cudaFuncAttributeMaxDynamicSharedMemorySize, SMEM_V);

    // 0) prep transposed bf16 splits
    prep_b_kernel<<<256, 256>>>(Wv,   pwvh, pwvl, 256);
    prep_b_kernel<<<256, 256>>>(Wout, pwoh, pwol, 256);
    prep_b_kernel<<<384, 256>>>(Woff, pwfh, pwfl, 384);
    prep_b_kernel<<<128, 256>>>(Wattn, pwah, pwal, 128);

    // 1) value = input_flatten @ Wv + bv   (128x256 mma tile)
    mma_gemm256_kernel<<<(NB * LEN_IN) / 128, 256, SMEM_V>>>(inp, pwvh, pwvl, bv, pv);

    // 2) off = query @ Woff + boff         (mma, N=384)
    {
        dim3 grid(3, (NB * LQ) / 128);
        mma_gemm_kernel<<<grid, 256, SMEM_MMA>>>(query, pwfh, pwfl, boff, po, 384);
    }
    // 3) attn logits = query @ Wattn + battn (mma, N=128)
    {
        dim3 grid(1, (NB * LQ) / 128);
        mma_gemm_kernel<<<grid, 256, SMEM_MMA>>>(query, pwah, pwal, battn, pa, 128);
    }
    // 4) softmax over 16
    softmax16_kernel<<<(NB * LQ * NHEADS + 255) / 256, 256>>>(pa, NB * LQ * NHEADS);

    // 5) deformable trilinear sampling -> g_mid
    sample_kernel<<<NB * LQ, 256>>>(refp, shapes, starts);

    // 6) out = g_mid @ Wout + bout          (128x256 mma tile)
    mma_gemm256_kernel<<<(NB * LQ) / 128, 256, SMEM_V>>>(pm, pwoh, pwol, bout, out);
}

// round 6
// speedup vs baseline: 5.5967x; 1.6768x over previous
#include <cuda_runtime.h>
#include <cuda_bf16.h>
#include <math.h>
#include <stdint.h>

#define NB      2
#define LQ      8192
#define LEN_IN  149760
#define DM      256
#define NHEADS  8
#define NLEV    4
#define NPTS    4
#define DHEAD   32

// ---------------- scratch (device globals; no cudaMalloc allowed) ----------
__device__ float g_value[(size_t)NB * LEN_IN * DM];                      // 306 MB
__device__ float g_off  [(size_t)NB * LQ * (NHEADS * NLEV * NPTS * 3)]; // 25 MB
__device__ float g_attn [(size_t)NB * LQ * (NHEADS * NLEV * NPTS)];     // 8 MB (raw logits)
__device__ float g_mid  [(size_t)NB * LQ * DM];                         // 16 MB
__device__ __nv_bfloat16 g_wv_hi [DM * DM];        // Wv^T    [N][K]
__device__ __nv_bfloat16 g_wv_lo [DM * DM];
__device__ __nv_bfloat16 g_wo_hi [DM * DM];        // Wout^T
__device__ __nv_bfloat16 g_wo_lo [DM * DM];
__device__ __nv_bfloat16 g_wf_hi [384 * DM];       // Woff^T  [384][256]
__device__ __nv_bfloat16 g_wf_lo [384 * DM];
__device__ __nv_bfloat16 g_wa_hi [128 * DM];       // Wattn^T [128][256]
__device__ __nv_bfloat16 g_wa_lo [128 * DM];

// ============================ PTX helpers ===================================
__device__ __forceinline__ uint32_t smem_u32(const void* p) {
    uint32_t a;
    asm("{ .reg .u64 t; cvta.to.shared.u64 t, %1; cvt.u32.u64 %0, t; }" : "=r"(a) : "l"(p));
    return a;
}
__device__ __forceinline__ void ldsm_x4(uint32_t* r, uint32_t addr) {
    asm volatile("ldmatrix.sync.aligned.m8n8.x4.shared.b16 {%0,%1,%2,%3}, [%4];"
        : "=r"(r[0]), "=r"(r[1]), "=r"(r[2]), "=r"(r[3]) : "r"(addr));
}
__device__ __forceinline__ void mma_bf16(float* d, const uint32_t* a,
                                         uint32_t b0, uint32_t b1) {
    asm volatile(
        "mma.sync.aligned.m16n8k16.row.col.f32.bf16.bf16.f32 "
        "{%0,%1,%2,%3}, {%4,%5,%6,%7}, {%8,%9}, {%0,%1,%2,%3};"
        : "+f"(d[0]), "+f"(d[1]), "+f"(d[2]), "+f"(d[3])
        : "r"(a[0]), "r"(a[1]), "r"(a[2]), "r"(a[3]), "r"(b0), "r"(b1));
}

// A fp32 -> (hi,lo) bf16 conversion of a float4, store to smem (uint2 each)
__device__ __forceinline__ void cvt_split_store(char* smem, int offHi, int offLo,
                                                uint32_t eoff, float4 v) {
    __nv_bfloat162 h01 = __floats2bfloat162_rn(v.x, v.y);
    __nv_bfloat162 h23 = __floats2bfloat162_rn(v.z, v.w);
    float lx = v.x - __bfloat162float(__low2bfloat16(h01));
    float ly = v.y - __bfloat162float(__high2bfloat16(h01));
    float lz = v.z - __bfloat162float(__low2bfloat16(h23));
    float lw = v.w - __bfloat162float(__high2bfloat16(h23));
    __nv_bfloat162 l01 = __floats2bfloat162_rn(lx, ly);
    __nv_bfloat162 l23 = __floats2bfloat162_rn(lz, lw);
    *(uint2*)(smem + offHi + eoff) = make_uint2(*(uint32_t*)&h01, *(uint32_t*)&h23);
    *(uint2*)(smem + offLo + eoff) = make_uint2(*(uint32_t*)&l01, *(uint32_t*)&l23);
}

// SMEM rows padded to 72 bf16 (144 B) -> conflict-free ldmatrix phases.
#define SA        72

// ---------------- generic 128x128-tile mma GEMM (off/attn) -----------------
#define OFF_AHI   0
#define OFF_ALO   18432
#define OFF_BHI   36864
#define OFF_BLO   55296
#define SMEM_MMA  73728

__global__ __launch_bounds__(256, 1) void mma_gemm_kernel(
    const float* __restrict__ A,
    const __nv_bfloat16* __restrict__ Bt_hi,
    const __nv_bfloat16* __restrict__ Bt_lo,
    const float* __restrict__ bias,
    float* __restrict__ C, int Nc)
{
    extern __shared__ char smem[];
    const uint32_t sb = smem_u32(smem);
    const int tid   = threadIdx.x;
    const int lane  = tid & 31;
    const int wid   = tid >> 5;
    const int mwarp = wid & 1;
    const int nwarp = wid >> 1;
    const int bn    = blockIdx.x;
    const size_t rowBase = (size_t)blockIdx.y * 128;

    float acc[4][4][4];
#pragma unroll
    for (int i = 0; i < 4; i++)
#pragma unroll
        for (int j = 0; j < 4; j++)
#pragma unroll
            for (int r = 0; r < 4; r++) acc[i][j][r] = 0.f;

    const int a_row = lane & 15, a_kh = lane >> 4;
    const uint32_t aAddrHi = sb + OFF_AHI +
        (uint32_t)(((mwarp * 64 + a_row) * SA + a_kh * 8) * 2);
    const int b_g = lane >> 3, b_r = lane & 7;
    const uint32_t bAddrHi = sb + OFF_BHI +
        (uint32_t)(((nwarp * 32 + (b_g >> 1) * 8 + b_r) * SA + (b_g & 1) * 8) * 2);

#pragma unroll 1
    for (int ch = 0; ch < 4; ch++) {
        const int k0 = ch * 64;
#pragma unroll
        for (int it = 0; it < 8; it++) {
            int idx = tid + it * 256;
            int row = idx >> 4, q = idx & 15;
            float4 v = *(const float4*)(A + (rowBase + row) * 256 + k0 + q * 4);
            cvt_split_store(smem, OFF_AHI, OFF_ALO,
                            (uint32_t)((row * SA + q * 4) * 2), v);
        }
#pragma unroll
        for (int it = 0; it < 4; it++) {
            int idx = tid + it * 256;
            int n = idx >> 3, q = idx & 7;
            uint32_t eoff = (uint32_t)((n * SA + q * 8) * 2);
            size_t goff = (size_t)(bn * 128 + n) * 256 + k0 + q * 8;
            *(uint4*)(smem + OFF_BHI + eoff) = *(const uint4*)(Bt_hi + goff);
            *(uint4*)(smem + OFF_BLO + eoff) = *(const uint4*)(Bt_lo + goff);
        }
        __syncthreads();

#pragma unroll
        for (int ks = 0; ks < 4; ks++) {
            const uint32_t kb = (uint32_t)(ks * 32);
            uint32_t ah[4][4], al[4][4];
#pragma unroll
            for (int mt = 0; mt < 4; mt++) {
                uint32_t ad = aAddrHi + (uint32_t)(mt * 16 * SA * 2) + kb;
                ldsm_x4(ah[mt], ad);
                ldsm_x4(al[mt], ad + (OFF_ALO - OFF_AHI));
            }
            uint32_t bh[2][4], bl[2][4];
#pragma unroll
            for (int pr = 0; pr < 2; pr++) {
                uint32_t bd = bAddrHi + (uint32_t)(pr * 16 * SA * 2) + kb;
                ldsm_x4(bh[pr], bd);
                ldsm_x4(bl[pr], bd + (OFF_BLO - OFF_BHI));
            }
#pragma unroll
            for (int mt = 0; mt < 4; mt++)
#pragma unroll
                for (int nt = 0; nt < 4; nt++) {
                    const int pr = nt >> 1, h = (nt & 1) * 2;
                    mma_bf16(acc[mt][nt], ah[mt], bh[pr][h], bh[pr][h + 1]);
                    mma_bf16(acc[mt][nt], ah[mt], bl[pr][h], bl[pr][h + 1]);
                    mma_bf16(acc[mt][nt], al[mt], bh[pr][h], bh[pr][h + 1]);
                }
        }
        __syncthreads();
    }

#pragma unroll
    for (int nt = 0; nt < 4; nt++) {
        const int col = bn * 128 + nwarp * 32 + nt * 8 + (lane & 3) * 2;
        const float2 bb = *(const float2*)(bias + col);
#pragma unroll
        for (int mt = 0; mt < 4; mt++) {
            const size_t row0 = rowBase + mwarp * 64 + mt * 16 + (lane >> 2);
            float2 o0, o1;
            o0.x = acc[mt][nt][0] + bb.x; o0.y = acc[mt][nt][1] + bb.y;
            o1.x = acc[mt][nt][2] + bb.x; o1.y = acc[mt][nt][3] + bb.y;
            *(float2*)(C + row0 * Nc + col)       = o0;
            *(float2*)(C + (row0 + 8) * Nc + col) = o1;
        }
    }
}

// ---------------- 128x256-tile mma GEMM (value / out projections) ----------
#define V_AHI   0
#define V_ALO   18432
#define V_BHI   36864
#define V_BLO   73728
#define SMEM_V  110592

__global__ __launch_bounds__(256, 1) void mma_gemm256_kernel(
    const float* __restrict__ A,
    const __nv_bfloat16* __restrict__ Bt_hi,
    const __nv_bfloat16* __restrict__ Bt_lo,
    const float* __restrict__ bias,
    float* __restrict__ C)
{
    extern __shared__ char smem[];
    const uint32_t sb = smem_u32(smem);
    const int tid   = threadIdx.x;
    const int lane  = tid & 31;
    const int wid   = tid >> 5;
    const int mwarp = wid & 1;
    const int nwarp = wid >> 1;
    const size_t rowBase = (size_t)blockIdx.x * 128;

    float acc[4][8][4];
#pragma unroll
    for (int i = 0; i < 4; i++)
#pragma unroll
        for (int j = 0; j < 8; j++)
#pragma unroll
            for (int r = 0; r < 4; r++) acc[i][j][r] = 0.f;

    const int a_row = lane & 15, a_kh = lane >> 4;
    const uint32_t aAddrHi = sb + V_AHI +
        (uint32_t)(((mwarp * 64 + a_row) * SA + a_kh * 8) * 2);
    const int b_g = lane >> 3, b_r = lane & 7;
    const uint32_t bAddrHi = sb + V_BHI +
        (uint32_t)(((nwarp * 64 + (b_g >> 1) * 8 + b_r) * SA + (b_g & 1) * 8) * 2);

#pragma unroll 1
    for (int ch = 0; ch < 4; ch++) {
        const int k0 = ch * 64;
#pragma unroll
        for (int it = 0; it < 8; it++) {
            int idx = tid + it * 256;
            int row = idx >> 4, q = idx & 15;
            float4 v = *(const float4*)(A + (rowBase + row) * 256 + k0 + q * 4);
            cvt_split_store(smem, V_AHI, V_ALO,
                            (uint32_t)((row * SA + q * 4) * 2), v);
        }
#pragma unroll
        for (int it = 0; it < 8; it++) {
            int idx = tid + it * 256;
            int n = idx >> 3, q = idx & 7;
            uint32_t eoff = (uint32_t)((n * SA + q * 8) * 2);
            size_t goff = (size_t)n * 256 + k0 + q * 8;
            *(uint4*)(smem + V_BHI + eoff) = *(const uint4*)(Bt_hi + goff);
            *(uint4*)(smem + V_BLO + eoff) = *(const uint4*)(Bt_lo + goff);
        }
        __syncthreads();

#pragma unroll
        for (int ks = 0; ks < 4; ks++) {
            const uint32_t kb = (uint32_t)(ks * 32);
            uint32_t ah[4][4], al[4][4];
#pragma unroll
            for (int mt = 0; mt < 4; mt++) {
                uint32_t ad = aAddrHi + (uint32_t)(mt * 16 * SA * 2) + kb;
                ldsm_x4(ah[mt], ad);
                ldsm_x4(al[mt], ad + (V_ALO - V_AHI));
            }
#pragma unroll
            for (int pr = 0; pr < 4; pr++) {
                uint32_t bh[4], bl[4];
                uint32_t bd = bAddrHi + (uint32_t)(pr * 16 * SA * 2) + kb;
                ldsm_x4(bh, bd);
                ldsm_x4(bl, bd + (V_BLO - V_BHI));
#pragma unroll
                for (int h2 = 0; h2 < 2; h2++) {
                    const int nt = pr * 2 + h2, h = h2 * 2;
#pragma unroll
                    for (int mt = 0; mt < 4; mt++) {
                        mma_bf16(acc[mt][nt], ah[mt], bh[h], bh[h + 1]);
                        mma_bf16(acc[mt][nt], ah[mt], bl[h], bl[h + 1]);
                        mma_bf16(acc[mt][nt], al[mt], bh[h], bh[h + 1]);
                    }
                }
            }
        }
        __syncthreads();
    }

#pragma unroll
    for (int nt = 0; nt < 8; nt++) {
        const int col = nwarp * 64 + nt * 8 + (lane & 3) * 2;
        const float2 bb = *(const float2*)(bias + col);
#pragma unroll
        for (int mt = 0; mt < 4; mt++) {
            const size_t row0 = rowBase + mwarp * 64 + mt * 16 + (lane >> 2);
            float2 o0, o1;
            o0.x = acc[mt][nt][0] + bb.x; o0.y = acc[mt][nt][1] + bb.y;
            o1.x = acc[mt][nt][2] + bb.x; o1.y = acc[mt][nt][3] + bb.y;
            *(float2*)(C + row0 * 256 + col)       = o0;
            *(float2*)(C + (row0 + 8) * 256 + col) = o1;
        }
    }
}

// ---- prep: W (256 x N row-major f32) -> transposed split bf16 [N][256] ----
__global__ void prep_b_kernel(const float* __restrict__ W,
                              __nv_bfloat16* __restrict__ bhi,
                              __nv_bfloat16* __restrict__ blo, int N)
{
    int idx = blockIdx.x * 256 + threadIdx.x;
    if (idx >= N * 256) return;
    int n = idx >> 8, k = idx & 255;
    float v = W[k * N + n];
    __nv_bfloat16 h = __float2bfloat16(v);
    bhi[idx] = h;
    blo[idx] = __float2bfloat16(v - __bfloat162float(h));
}

// ====== fused softmax + trilinear deformable sampling ======================
// Block = 256 threads = 8 warps, warp = head; block per query.
// Phase 1 (cooperative): lane (o = lane&15, chalf = lane>>4) computes the
//   softmax weight for point o and the (voxel index, attn*weight) pairs for
//   corners chalf*4..chalf*4+3 — uniform math executed once, not 32x.
// Phase 2: broadcast pairs via shfl; 32 lanes gather 128B lines and fma.
__global__ __launch_bounds__(256) void sample_kernel(
    const float* __restrict__ rp,
    const int*   __restrict__ shapes,
    const int*   __restrict__ starts)
{
    const int q    = blockIdx.x;
    const int h    = threadIdx.x >> 5;
    const int lane = threadIdx.x & 31;

    __shared__ float s_rp[NLEV * 3];
    __shared__ int   s_dim[NLEV * 3];
    __shared__ int   s_start[NLEV];
    if (threadIdx.x < NLEV * 3) {
        s_rp[threadIdx.x]  = rp[(size_t)q * (NLEV * 3) + threadIdx.x];
        s_dim[threadIdx.x] = shapes[threadIdx.x];
    }
    if (threadIdx.x < NLEV) s_start[threadIdx.x] = starts[threadIdx.x];
    __syncthreads();

    const int n = q / LQ;
    const int o     = lane & 15;        // point 0..15
    const int chalf = lane >> 4;        // corner half 0/1
    const int l     = o >> 2;           // level of this point

    // ---- phase 1: softmax over the 16 logits (width-16 reduction) ----
    float logit = g_attn[(size_t)q * (NHEADS * 16) + h * 16 + o];
    float m = logit;
#pragma unroll
    for (int s = 8; s > 0; s >>= 1)
        m = fmaxf(m, __shfl_xor_sync(0xffffffffu, m, s, 16));
    float e = __expf(logit - m);
    float ssum = e;
#pragma unroll
    for (int s = 8; s > 0; s >>= 1)
        ssum += __shfl_xor_sync(0xffffffffu, ssum, s, 16);
    const float a = e / ssum;

    // ---- phase 1: coordinates + per-corner (idx, a*w) ----
    const float* offq = g_off + (size_t)q * (NHEADS * 48) + h * 48 + o * 3;
    const int D = s_dim[l * 3 + 0];
    const int H = s_dim[l * 3 + 1];
    const int W = s_dim[l * 3 + 2];
    const float x = (s_rp[l * 3 + 0] + offq[0] / (float)W) * (float)W - 0.5f;
    const float y = (s_rp[l * 3 + 1] + offq[1] / (float)H) * (float)H - 0.5f;
    const float z = (s_rp[l * 3 + 2] + offq[2] / (float)D) * (float)D - 0.5f;
    const float x0f = floorf(x), y0f = floorf(y), z0f = floorf(z);
    const int   x0 = (int)x0f,   y0 = (int)y0f,   z0 = (int)z0f;
    const float fx = x - x0f,    fy = y - y0f,    fz = z - z0f;

    int   idxr[4];
    float awr [4];
#pragma unroll
    for (int cc = 0; cc < 4; cc++) {
        const int c  = chalf * 4 + cc;
        const int dx = c & 1, dy = (c >> 1) & 1, dz = (c >> 2) & 1;
        const int xi = x0 + dx, yi = y0 + dy, zi = z0 + dz;
        const float w = (dx ? fx : 1.f - fx)
                      * (dy ? fy : 1.f - fy)
                      * (dz ? fz : 1.f - fz);
        const bool valid = (xi >= 0) & (xi < W) & (yi >= 0) & (yi < H) &
                           (zi >= 0) & (zi < D) & (w != 0.f);
        idxr[cc] = valid ? ((zi * H + yi) * W + xi) : -1;
        awr[cc]  = a * w;
    }

    // ---- phase 2: gather ----
    const float* vb[NLEV];
#pragma unroll
    for (int lv = 0; lv < NLEV; lv++)
        vb[lv] = g_value + ((size_t)(n * LEN_IN + s_start[lv])) * DM
               + h * DHEAD + lane;

    float acc0 = 0.f, acc1 = 0.f;
#pragma unroll
    for (int o2 = 0; o2 < 16; o2++) {
        const int lv = o2 >> 2;
#pragma unroll
        for (int c = 0; c < 8; c++) {
            const int src = o2 + (c >> 2) * 16;
            const int cc  = c & 3;
            const int   idx = __shfl_sync(0xffffffffu, idxr[cc], src);
            const float aw  = __shfl_sync(0xffffffffu, awr[cc],  src);
            if (idx >= 0) {
                const float vv = __ldg(vb[lv] + (size_t)idx * DM);
                if (c & 1) acc1 = fmaf(aw, vv, acc1);
                else       acc0 = fmaf(aw, vv, acc0);
            }
        }
    }
    g_mid[(size_t)q * DM + h * DHEAD + lane] = acc0 + acc1;
}

// ---------------------------------------------------------------------------
extern "C" void kernel_launch(void* const* d_in, const int* in_sizes, int n_in,
                              void* d_out, int out_size)
{
    const float* query  = (const float*)d_in[0];
    const float* refp   = (const float*)d_in[1];
    const float* inp    = (const float*)d_in[2];
    const int*   shapes = (const int*)  d_in[3];
    const int*   starts = (const int*)  d_in[4];
    const float* Wv     = (const float*)d_in[5];
    const float* bv     = (const float*)d_in[6];
    const float* Woff   = (const float*)d_in[7];
    const float* boff   = (const float*)d_in[8];
    const float* Wattn  = (const float*)d_in[9];
    const float* battn  = (const float*)d_in[10];
    const float* Wout   = (const float*)d_in[11];
    const float* bout   = (const float*)d_in[12];
    float* out = (float*)d_out;

    float *pv, *po, *pa, *pm;
    __nv_bfloat16 *pwvh, *pwvl, *pwoh, *pwol, *pwfh, *pwfl, *pwah, *pwal;
    cudaGetSymbolAddress((void**)&pv, g_value);
    cudaGetSymbolAddress((void**)&po, g_off);
    cudaGetSymbolAddress((void**)&pa, g_attn);
    cudaGetSymbolAddress((void**)&pm, g_mid);
    cudaGetSymbolAddress((void**)&pwvh, g_wv_hi);
    cudaGetSymbolAddress((void**)&pwvl, g_wv_lo);
    cudaGetSymbolAddress((void**)&pwoh, g_wo_hi);
    cudaGetSymbolAddress((void**)&pwol, g_wo_lo);
    cudaGetSymbolAddress((void**)&pwfh, g_wf_hi);
    cudaGetSymbolAddress((void**)&pwfl, g_wf_lo);
    cudaGetSymbolAddress((void**)&pwah, g_wa_hi);
    cudaGetSymbolAddress((void**)&pwal, g_wa_lo);

    cudaFuncSetAttribute(mma_gemm_kernel,
                         cudaFuncAttributeMaxDynamicSharedMemorySize, SMEM_MMA);
    cudaFuncSetAttribute(mma_gemm256_kernel,
                         cudaFuncAttributeMaxDynamicSharedMemorySize, SMEM_V);

    // 0) prep transposed bf16 splits
    prep_b_kernel<<<256, 256>>>(Wv,   pwvh, pwvl, 256);
    prep_b_kernel<<<256, 256>>>(Wout, pwoh, pwol, 256);
    prep_b_kernel<<<384, 256>>>(Woff, pwfh, pwfl, 384);
    prep_b_kernel<<<128, 256>>>(Wattn, pwah, pwal, 128);

    // 1) value = input_flatten @ Wv + bv   (128x256 mma tile)
    mma_gemm256_kernel<<<(NB * LEN_IN) / 128, 256, SMEM_V>>>(inp, pwvh, pwvl, bv, pv);

    // 2) off = query @ Woff + boff         (mma, N=384)
    {
        dim3 grid(3, (NB * LQ) / 128);
        mma_gemm_kernel<<<grid, 256, SMEM_MMA>>>(query, pwfh, pwfl, boff, po, 384);
    }
    // 3) attn logits = query @ Wattn + battn (mma, N=128) — softmax fused in sampler
    {
        dim3 grid(1, (NB * LQ) / 128);
        mma_gemm_kernel<<<grid, 256, SMEM_MMA>>>(query, pwah, pwal, battn, pa, 128);
    }
    // 4) fused softmax + deformable trilinear sampling -> g_mid
    sample_kernel<<<NB * LQ, 256>>>(refp, shapes, starts);

    // 5) out = g_mid @ Wout + bout          (128x256 mma tile)
    mma_gemm256_kernel<<<(NB * LQ) / 128, 256, SMEM_V>>>(pm, pwoh, pwol, bout, out);
}

// round 7
// speedup vs baseline: 5.7902x; 1.0346x over previous
#include <cuda_runtime.h>
#include <cuda_bf16.h>
#include <math.h>
#include <stdint.h>

#define NB      2
#define LQ      8192
#define LEN_IN  149760
#define DM      256
#define NHEADS  8
#define NLEV    4
#define NPTS    4
#define DHEAD   32

// ---------------- scratch (device globals; no cudaMalloc allowed) ----------
__device__ float g_value[(size_t)NB * LEN_IN * DM];                      // 306 MB
__device__ float g_off  [(size_t)NB * LQ * (NHEADS * NLEV * NPTS * 3)]; // 25 MB
__device__ float g_attn [(size_t)NB * LQ * (NHEADS * NLEV * NPTS)];     // 8 MB (raw logits)
__device__ float g_mid  [(size_t)NB * LQ * DM];                         // 16 MB
__device__ __nv_bfloat16 g_wv_hi [DM * DM];        // Wv^T    [N][K]
__device__ __nv_bfloat16 g_wv_lo [DM * DM];
__device__ __nv_bfloat16 g_wo_hi [DM * DM];        // Wout^T
__device__ __nv_bfloat16 g_wo_lo [DM * DM];
__device__ __nv_bfloat16 g_wf_hi [384 * DM];       // Woff^T  [384][256]
__device__ __nv_bfloat16 g_wf_lo [384 * DM];
__device__ __nv_bfloat16 g_wa_hi [128 * DM];       // Wattn^T [128][256]
__device__ __nv_bfloat16 g_wa_lo [128 * DM];

// ============================ PTX helpers ===================================
__device__ __forceinline__ uint32_t smem_u32(const void* p) {
    uint32_t a;
    asm("{ .reg .u64 t; cvta.to.shared.u64 t, %1; cvt.u32.u64 %0, t; }" : "=r"(a) : "l"(p));
    return a;
}
__device__ __forceinline__ void ldsm_x4(uint32_t* r, uint32_t addr) {
    asm volatile("ldmatrix.sync.aligned.m8n8.x4.shared.b16 {%0,%1,%2,%3}, [%4];"
        : "=r"(r[0]), "=r"(r[1]), "=r"(r[2]), "=r"(r[3]) : "r"(addr));
}
__device__ __forceinline__ void mma_bf16(float* d, const uint32_t* a,
                                         uint32_t b0, uint32_t b1) {
    asm volatile(
        "mma.sync.aligned.m16n8k16.row.col.f32.bf16.bf16.f32 "
        "{%0,%1,%2,%3}, {%4,%5,%6,%7}, {%8,%9}, {%0,%1,%2,%3};"
        : "+f"(d[0]), "+f"(d[1]), "+f"(d[2]), "+f"(d[3])
        : "r"(a[0]), "r"(a[1]), "r"(a[2]), "r"(a[3]), "r"(b0), "r"(b1));
}
#define CP_ASYNC16(dst, src) \
    asm volatile("cp.async.cg.shared.global [%0], [%1], 16;" :: "r"(dst), "l"(src))
#define CP_COMMIT() asm volatile("cp.async.commit_group;" ::: "memory")
#define CP_WAIT(n)  asm volatile("cp.async.wait_group %0;" :: "n"(n) : "memory")

// A fp32 -> (hi,lo) bf16 conversion of a float4, store to smem (uint2 each)
__device__ __forceinline__ void cvt_split_store(char* smem, int offHi, int offLo,
                                                uint32_t eoff, float4 v) {
    __nv_bfloat162 h01 = __floats2bfloat162_rn(v.x, v.y);
    __nv_bfloat162 h23 = __floats2bfloat162_rn(v.z, v.w);
    float lx = v.x - __bfloat162float(__low2bfloat16(h01));
    float ly = v.y - __bfloat162float(__high2bfloat16(h01));
    float lz = v.z - __bfloat162float(__low2bfloat16(h23));
    float lw = v.w - __bfloat162float(__high2bfloat16(h23));
    __nv_bfloat162 l01 = __floats2bfloat162_rn(lx, ly);
    __nv_bfloat162 l23 = __floats2bfloat162_rn(lz, lw);
    *(uint2*)(smem + offHi + eoff) = make_uint2(*(uint32_t*)&h01, *(uint32_t*)&h23);
    *(uint2*)(smem + offLo + eoff) = make_uint2(*(uint32_t*)&l01, *(uint32_t*)&l23);
}

// SMEM rows padded to 72 bf16 (144 B) -> conflict-free ldmatrix phases.
#define SA        72

// ---------------- generic 128x128-tile mma GEMM (off/attn) -----------------
#define OFF_AHI   0
#define OFF_ALO   18432
#define OFF_BHI   36864
#define OFF_BLO   55296
#define SMEM_MMA  73728

__global__ __launch_bounds__(256, 1) void mma_gemm_kernel(
    const float* __restrict__ A,
    const __nv_bfloat16* __restrict__ Bt_hi,
    const __nv_bfloat16* __restrict__ Bt_lo,
    const float* __restrict__ bias,
    float* __restrict__ C, int Nc)
{
    extern __shared__ char smem[];
    const uint32_t sb = smem_u32(smem);
    const int tid   = threadIdx.x;
    const int lane  = tid & 31;
    const int wid   = tid >> 5;
    const int mwarp = wid & 1;
    const int nwarp = wid >> 1;
    const int bn    = blockIdx.x;
    const size_t rowBase = (size_t)blockIdx.y * 128;

    float acc[4][4][4];
#pragma unroll
    for (int i = 0; i < 4; i++)
#pragma unroll
        for (int j = 0; j < 4; j++)
#pragma unroll
            for (int r = 0; r < 4; r++) acc[i][j][r] = 0.f;

    const int a_row = lane & 15, a_kh = lane >> 4;
    const uint32_t aAddrHi = sb + OFF_AHI +
        (uint32_t)(((mwarp * 64 + a_row) * SA + a_kh * 8) * 2);
    const int b_g = lane >> 3, b_r = lane & 7;
    const uint32_t bAddrHi = sb + OFF_BHI +
        (uint32_t)(((nwarp * 32 + (b_g >> 1) * 8 + b_r) * SA + (b_g & 1) * 8) * 2);

#pragma unroll 1
    for (int ch = 0; ch < 4; ch++) {
        const int k0 = ch * 64;
#pragma unroll
        for (int it = 0; it < 8; it++) {
            int idx = tid + it * 256;
            int row = idx >> 4, q = idx & 15;
            float4 v = *(const float4*)(A + (rowBase + row) * 256 + k0 + q * 4);
            cvt_split_store(smem, OFF_AHI, OFF_ALO,
                            (uint32_t)((row * SA + q * 4) * 2), v);
        }
#pragma unroll
        for (int it = 0; it < 4; it++) {
            int idx = tid + it * 256;
            int n = idx >> 3, q = idx & 7;
            uint32_t eoff = (uint32_t)((n * SA + q * 8) * 2);
            size_t goff = (size_t)(bn * 128 + n) * 256 + k0 + q * 8;
            *(uint4*)(smem + OFF_BHI + eoff) = *(const uint4*)(Bt_hi + goff);
            *(uint4*)(smem + OFF_BLO + eoff) = *(const uint4*)(Bt_lo + goff);
        }
        __syncthreads();

#pragma unroll
        for (int ks = 0; ks < 4; ks++) {
            const uint32_t kb = (uint32_t)(ks * 32);
            uint32_t ah[4][4], al[4][4];
#pragma unroll
            for (int mt = 0; mt < 4; mt++) {
                uint32_t ad = aAddrHi + (uint32_t)(mt * 16 * SA * 2) + kb;
                ldsm_x4(ah[mt], ad);
                ldsm_x4(al[mt], ad + (OFF_ALO - OFF_AHI));
            }
            uint32_t bh[2][4], bl[2][4];
#pragma unroll
            for (int pr = 0; pr < 2; pr++) {
                uint32_t bd = bAddrHi + (uint32_t)(pr * 16 * SA * 2) + kb;
                ldsm_x4(bh[pr], bd);
                ldsm_x4(bl[pr], bd + (OFF_BLO - OFF_BHI));
            }
#pragma unroll
            for (int mt = 0; mt < 4; mt++)
#pragma unroll
                for (int nt = 0; nt < 4; nt++) {
                    const int pr = nt >> 1, h = (nt & 1) * 2;
                    mma_bf16(acc[mt][nt], ah[mt], bh[pr][h], bh[pr][h + 1]);
                    mma_bf16(acc[mt][nt], ah[mt], bl[pr][h], bl[pr][h + 1]);
                    mma_bf16(acc[mt][nt], al[mt], bh[pr][h], bh[pr][h + 1]);
                }
        }
        __syncthreads();
    }

#pragma unroll
    for (int nt = 0; nt < 4; nt++) {
        const int col = bn * 128 + nwarp * 32 + nt * 8 + (lane & 3) * 2;
        const float2 bb = *(const float2*)(bias + col);
#pragma unroll
        for (int mt = 0; mt < 4; mt++) {
            const size_t row0 = rowBase + mwarp * 64 + mt * 16 + (lane >> 2);
            float2 o0, o1;
            o0.x = acc[mt][nt][0] + bb.x; o0.y = acc[mt][nt][1] + bb.y;
            o1.x = acc[mt][nt][2] + bb.x; o1.y = acc[mt][nt][3] + bb.y;
            *(float2*)(C + row0 * Nc + col)       = o0;
            *(float2*)(C + (row0 + 8) * Nc + col) = o1;
        }
    }
}

// ------- pipelined 128x256-tile mma GEMM (value / out projections) ---------
// A prefetched into regs one chunk ahead; B double-buffered via cp.async.
// SMEM: A_hi 0 (18KB), A_lo 18432, B bufs at 36864 + buf*73728 (hi, lo 36864 apart)
#define V_AHI     0
#define V_ALO     18432
#define V_B0      36864
#define V_BSTRIDE 73728
#define SMEM_V    184320

__global__ __launch_bounds__(256, 1) void mma_gemm256_kernel(
    const float* __restrict__ A,
    const __nv_bfloat16* __restrict__ Bt_hi,
    const __nv_bfloat16* __restrict__ Bt_lo,
    const float* __restrict__ bias,
    float* __restrict__ C)
{
    extern __shared__ char smem[];
    const uint32_t sb = smem_u32(smem);
    const int tid   = threadIdx.x;
    const int lane  = tid & 31;
    const int wid   = tid >> 5;
    const int mwarp = wid & 1;
    const int nwarp = wid >> 1;
    const size_t rowBase = (size_t)blockIdx.x * 128;

    float acc[4][8][4];
#pragma unroll
    for (int i = 0; i < 4; i++)
#pragma unroll
        for (int j = 0; j < 8; j++)
#pragma unroll
            for (int r = 0; r < 4; r++) acc[i][j][r] = 0.f;

    const int a_row = lane & 15, a_kh = lane >> 4;
    const uint32_t aAddrHi = sb + V_AHI +
        (uint32_t)(((mwarp * 64 + a_row) * SA + a_kh * 8) * 2);
    const int b_g = lane >> 3, b_r = lane & 7;
    const uint32_t bAddrBase = sb + V_B0 +
        (uint32_t)(((nwarp * 64 + (b_g >> 1) * 8 + b_r) * SA + (b_g & 1) * 8) * 2);

    // per-thread load coords
    const int arow_ld = tid >> 1;                 // with it-offset below
    const int bq = tid & 7, bn_ld = tid >> 3;     // B: 32 n-rows per it step

    // ---- prologue: prefetch A(0) regs, cp.async B(0) ----
    float4 apre[8];
#pragma unroll
    for (int it = 0; it < 8; it++) {
        int idx = tid + it * 256;
        int row = idx >> 4, q = idx & 15;
        apre[it] = *(const float4*)(A + (rowBase + row) * 256 + 0 + q * 4);
    }
#pragma unroll
    for (int it = 0; it < 8; it++) {
        int idx = tid + it * 256;
        int n = idx >> 3, q = idx & 7;
        uint32_t eoff = (uint32_t)((n * SA + q * 8) * 2);
        CP_ASYNC16(sb + V_B0 + eoff, Bt_hi + (size_t)n * 256 + q * 8);
        CP_ASYNC16(sb + V_B0 + 36864 + eoff, Bt_lo + (size_t)n * 256 + q * 8);
    }
    CP_COMMIT();

#pragma unroll 1
    for (int ch = 0; ch < 4; ch++) {
        const int buf = ch & 1;

        // convert prefetched A regs -> smem (prev mma done: trailing sync)
#pragma unroll
        for (int it = 0; it < 8; it++) {
            int idx = tid + it * 256;
            int row = idx >> 4, q = idx & 15;
            cvt_split_store(smem, V_AHI, V_ALO,
                            (uint32_t)((row * SA + q * 4) * 2), apre[it]);
        }
        // issue cp.async for B(ch+1)
        if (ch < 3) {
            const int k1 = (ch + 1) * 64;
            const uint32_t bsm = sb + V_B0 + (uint32_t)((buf ^ 1) * V_BSTRIDE);
#pragma unroll
            for (int it = 0; it < 8; it++) {
                int idx = tid + it * 256;
                int n = idx >> 3, q = idx & 7;
                uint32_t eoff = (uint32_t)((n * SA + q * 8) * 2);
                CP_ASYNC16(bsm + eoff,         Bt_hi + (size_t)n * 256 + k1 + q * 8);
                CP_ASYNC16(bsm + 36864 + eoff, Bt_lo + (size_t)n * 256 + k1 + q * 8);
            }
            CP_COMMIT();
            CP_WAIT(1);           // B(ch) done, B(ch+1) in flight
        } else {
            CP_WAIT(0);
        }
        __syncthreads();

        // prefetch A(ch+1) into regs — drains behind the mma below
        if (ch < 3) {
            const int k1 = (ch + 1) * 64;
#pragma unroll
            for (int it = 0; it < 8; it++) {
                int idx = tid + it * 256;
                int row = idx >> 4, q = idx & 15;
                apre[it] = *(const float4*)(A + (rowBase + row) * 256 + k1 + q * 4);
            }
        }

        const uint32_t bAddrHi = bAddrBase + (uint32_t)(buf * V_BSTRIDE);
#pragma unroll
        for (int ks = 0; ks < 4; ks++) {
            const uint32_t kb = (uint32_t)(ks * 32);
            uint32_t ah[4][4], al[4][4];
#pragma unroll
            for (int mt = 0; mt < 4; mt++) {
                uint32_t ad = aAddrHi + (uint32_t)(mt * 16 * SA * 2) + kb;
                ldsm_x4(ah[mt], ad);
                ldsm_x4(al[mt], ad + (V_ALO - V_AHI));
            }
#pragma unroll
            for (int pr = 0; pr < 4; pr++) {
                uint32_t bh[4], bl[4];
                uint32_t bd = bAddrHi + (uint32_t)(pr * 16 * SA * 2) + kb;
                ldsm_x4(bh, bd);
                ldsm_x4(bl, bd + 36864);
#pragma unroll
                for (int h2 = 0; h2 < 2; h2++) {
                    const int nt = pr * 2 + h2, h = h2 * 2;
#pragma unroll
                    for (int mt = 0; mt < 4; mt++) {
                        mma_bf16(acc[mt][nt], ah[mt], bh[h], bh[h + 1]);
                        mma_bf16(acc[mt][nt], ah[mt], bl[h], bl[h + 1]);
                        mma_bf16(acc[mt][nt], al[mt], bh[h], bh[h + 1]);
                    }
                }
            }
        }
        __syncthreads();
    }

#pragma unroll
    for (int nt = 0; nt < 8; nt++) {
        const int col = nwarp * 64 + nt * 8 + (lane & 3) * 2;
        const float2 bb = *(const float2*)(bias + col);
#pragma unroll
        for (int mt = 0; mt < 4; mt++) {
            const size_t row0 = rowBase + mwarp * 64 + mt * 16 + (lane >> 2);
            float2 o0, o1;
            o0.x = acc[mt][nt][0] + bb.x; o0.y = acc[mt][nt][1] + bb.y;
            o1.x = acc[mt][nt][2] + bb.x; o1.y = acc[mt][nt][3] + bb.y;
            *(float2*)(C + row0 * 256 + col)       = o0;
            *(float2*)(C + (row0 + 8) * 256 + col) = o1;
        }
    }
}

// ---- prep: W (256 x N row-major f32) -> transposed split bf16 [N][256] ----
__global__ void prep_b_kernel(const float* __restrict__ W,
                              __nv_bfloat16* __restrict__ bhi,
                              __nv_bfloat16* __restrict__ blo, int N)
{
    int idx = blockIdx.x * 256 + threadIdx.x;
    if (idx >= N * 256) return;
    int n = idx >> 8, k = idx & 255;
    float v = W[k * N + n];
    __nv_bfloat16 h = __float2bfloat16(v);
    bhi[idx] = h;
    blo[idx] = __float2bfloat16(v - __bfloat162float(h));
}

// ====== fused softmax + trilinear deformable sampling ======================
__global__ __launch_bounds__(256) void sample_kernel(
    const float* __restrict__ rp,
    const int*   __restrict__ shapes,
    const int*   __restrict__ starts)
{
    const int q    = blockIdx.x;
    const int h    = threadIdx.x >> 5;
    const int lane = threadIdx.x & 31;

    __shared__ float s_rp[NLEV * 3];
    __shared__ int   s_dim[NLEV * 3];
    __shared__ int   s_start[NLEV];
    if (threadIdx.x < NLEV * 3) {
        s_rp[threadIdx.x]  = rp[(size_t)q * (NLEV * 3) + threadIdx.x];
        s_dim[threadIdx.x] = shapes[threadIdx.x];
    }
    if (threadIdx.x < NLEV) s_start[threadIdx.x] = starts[threadIdx.x];
    __syncthreads();

    const int n = q / LQ;
    const int o     = lane & 15;
    const int chalf = lane >> 4;
    const int l     = o >> 2;

    float logit = g_attn[(size_t)q * (NHEADS * 16) + h * 16 + o];
    float m = logit;
#pragma unroll
    for (int s = 8; s > 0; s >>= 1)
        m = fmaxf(m, __shfl_xor_sync(0xffffffffu, m, s, 16));
    float e = __expf(logit - m);
    float ssum = e;
#pragma unroll
    for (int s = 8; s > 0; s >>= 1)
        ssum += __shfl_xor_sync(0xffffffffu, ssum, s, 16);
    const float a = e / ssum;

    const float* offq = g_off + (size_t)q * (NHEADS * 48) + h * 48 + o * 3;
    const int D = s_dim[l * 3 + 0];
    const int H = s_dim[l * 3 + 1];
    const int W = s_dim[l * 3 + 2];
    const float x = (s_rp[l * 3 + 0] + offq[0] / (float)W) * (float)W - 0.5f;
    const float y = (s_rp[l * 3 + 1] + offq[1] / (float)H) * (float)H - 0.5f;
    const float z = (s_rp[l * 3 + 2] + offq[2] / (float)D) * (float)D - 0.5f;
    const float x0f = floorf(x), y0f = floorf(y), z0f = floorf(z);
    const int   x0 = (int)x0f,   y0 = (int)y0f,   z0 = (int)z0f;
    const float fx = x - x0f,    fy = y - y0f,    fz = z - z0f;

    int   idxr[4];
    float awr [4];
#pragma unroll
    for (int cc = 0; cc < 4; cc++) {
        const int c  = chalf * 4 + cc;
        const int dx = c & 1, dy = (c >> 1) & 1, dz = (c >> 2) & 1;
        const int xi = x0 + dx, yi = y0 + dy, zi = z0 + dz;
        const float w = (dx ? fx : 1.f - fx)
                      * (dy ? fy : 1.f - fy)
                      * (dz ? fz : 1.f - fz);
        const bool valid = (xi >= 0) & (xi < W) & (yi >= 0) & (yi < H) &
                           (zi >= 0) & (zi < D) & (w != 0.f);
        idxr[cc] = valid ? ((zi * H + yi) * W + xi) : -1;
        awr[cc]  = a * w;
    }

    const float* vb[NLEV];
#pragma unroll
    for (int lv = 0; lv < NLEV; lv++)
        vb[lv] = g_value + ((size_t)(n * LEN_IN + s_start[lv])) * DM
               + h * DHEAD + lane;

    float acc0 = 0.f, acc1 = 0.f;
#pragma unroll
    for (int o2 = 0; o2 < 16; o2++) {
        const int lv = o2 >> 2;
#pragma unroll
        for (int c = 0; c < 8; c++) {
            const int src = o2 + (c >> 2) * 16;
            const int cc  = c & 3;
            const int   idx = __shfl_sync(0xffffffffu, idxr[cc], src);
            const float aw  = __shfl_sync(0xffffffffu, awr[cc],  src);
            if (idx >= 0) {
                const float vv = __ldg(vb[lv] + (size_t)idx * DM);
                if (c & 1) acc1 = fmaf(aw, vv, acc1);
                else       acc0 = fmaf(aw, vv, acc0);
            }
        }
    }
    g_mid[(size_t)q * DM + h * DHEAD + lane] = acc0 + acc1;
}

// ---------------------------------------------------------------------------
extern "C" void kernel_launch(void* const* d_in, const int* in_sizes, int n_in,
                              void* d_out, int out_size)
{
    const float* query  = (const float*)d_in[0];
    const float* refp   = (const float*)d_in[1];
    const float* inp    = (const float*)d_in[2];
    const int*   shapes = (const int*)  d_in[3];
    const int*   starts = (const int*)  d_in[4];
    const float* Wv     = (const float*)d_in[5];
    const float* bv     = (const float*)d_in[6];
    const float* Woff   = (const float*)d_in[7];
    const float* boff   = (const float*)d_in[8];
    const float* Wattn  = (const float*)d_in[9];
    const float* battn  = (const float*)d_in[10];
    const float* Wout   = (const float*)d_in[11];
    const float* bout   = (const float*)d_in[12];
    float* out = (float*)d_out;

    float *pv, *po, *pa, *pm;
    __nv_bfloat16 *pwvh, *pwvl, *pwoh, *pwol, *pwfh, *pwfl, *pwah, *pwal;
    cudaGetSymbolAddress((void**)&pv, g_value);
    cudaGetSymbolAddress((void**)&po, g_off);
    cudaGetSymbolAddress((void**)&pa, g_attn);
    cudaGetSymbolAddress((void**)&pm, g_mid);
    cudaGetSymbolAddress((void**)&pwvh, g_wv_hi);
    cudaGetSymbolAddress((void**)&pwvl, g_wv_lo);
    cudaGetSymbolAddress((void**)&pwoh, g_wo_hi);
    cudaGetSymbolAddress((void**)&pwol, g_wo_lo);
    cudaGetSymbolAddress((void**)&pwfh, g_wf_hi);
    cudaGetSymbolAddress((void**)&pwfl, g_wf_lo);
    cudaGetSymbolAddress((void**)&pwah, g_wa_hi);
    cudaGetSymbolAddress((void**)&pwal, g_wa_lo);

    cudaFuncSetAttribute(mma_gemm_kernel,
                         cudaFuncAttributeMaxDynamicSharedMemorySize, SMEM_MMA);
    cudaFuncSetAttribute(mma_gemm256_kernel,
                         cudaFuncAttributeMaxDynamicSharedMemorySize, SMEM_V);

    // 0) prep transposed bf16 splits
    prep_b_kernel<<<256, 256>>>(Wv,   pwvh, pwvl, 256);
    prep_b_kernel<<<256, 256>>>(Wout, pwoh, pwol, 256);
    prep_b_kernel<<<384, 256>>>(Woff, pwfh, pwfl, 384);
    prep_b_kernel<<<128, 256>>>(Wattn, pwah, pwal, 128);

    // 1) value = input_flatten @ Wv + bv   (pipelined 128x256 mma tile)
    mma_gemm256_kernel<<<(NB * LEN_IN) / 128, 256, SMEM_V>>>(inp, pwvh, pwvl, bv, pv);

    // 2) off = query @ Woff + boff         (mma, N=384)
    {
        dim3 grid(3, (NB * LQ) / 128);
        mma_gemm_kernel<<<grid, 256, SMEM_MMA>>>(query, pwfh, pwfl, boff, po, 384);
    }
    // 3) attn logits = query @ Wattn + battn (mma, N=128)
    {
        dim3 grid(1, (NB * LQ) / 128);
        mma_gemm_kernel<<<grid, 256, SMEM_MMA>>>(query, pwah, pwal, battn, pa, 128);
    }
    // 4) fused softmax + deformable trilinear sampling -> g_mid
    sample_kernel<<<NB * LQ, 256>>>(refp, shapes, starts);

    // 5) out = g_mid @ Wout + bout          (pipelined 128x256 mma tile)
    mma_gemm256_kernel<<<(NB * LQ) / 128, 256, SMEM_V>>>(pm, pwoh, pwol, bout, out);
}

// round 8
// speedup vs baseline: 5.9465x; 1.0270x over previous
#include <cuda_runtime.h>
#include <cuda_bf16.h>
#include <cuda_fp16.h>
#include <math.h>
#include <stdint.h>

#define NB      2
#define LQ      8192
#define LEN_IN  149760
#define DM      256
#define NHEADS  8
#define NLEV    4
#define NPTS    4
#define DHEAD   32

// ---------------- scratch (device globals; no cudaMalloc allowed) ----------
__device__ __half g_value[(size_t)NB * LEN_IN * DM];                     // 153 MB
__device__ float  g_offattn[(size_t)NB * LQ * 512];                     // 33.5 MB (off 0..383, logits 384..511)
__device__ float  g_mid  [(size_t)NB * LQ * DM];                        // 16 MB
__device__ __nv_bfloat16 g_wv_hi [DM * DM];        // Wv^T    [N][K]
__device__ __nv_bfloat16 g_wv_lo [DM * DM];
__device__ __nv_bfloat16 g_wo_hi [DM * DM];        // Wout^T
__device__ __nv_bfloat16 g_wo_lo [DM * DM];
__device__ __nv_bfloat16 g_wfa_hi[512 * DM];       // [Woff|Wattn]^T [512][256]
__device__ __nv_bfloat16 g_wfa_lo[512 * DM];
__device__ float  g_bfa[512];                      // [boff|battn]

// ============================ PTX helpers ===================================
__device__ __forceinline__ uint32_t smem_u32(const void* p) {
    uint32_t a;
    asm("{ .reg .u64 t; cvta.to.shared.u64 t, %1; cvt.u32.u64 %0, t; }" : "=r"(a) : "l"(p));
    return a;
}
__device__ __forceinline__ void ldsm_x4(uint32_t* r, uint32_t addr) {
    asm volatile("ldmatrix.sync.aligned.m8n8.x4.shared.b16 {%0,%1,%2,%3}, [%4];"
        : "=r"(r[0]), "=r"(r[1]), "=r"(r[2]), "=r"(r[3]) : "r"(addr));
}
__device__ __forceinline__ void mma_bf16(float* d, const uint32_t* a,
                                         uint32_t b0, uint32_t b1) {
    asm volatile(
        "mma.sync.aligned.m16n8k16.row.col.f32.bf16.bf16.f32 "
        "{%0,%1,%2,%3}, {%4,%5,%6,%7}, {%8,%9}, {%0,%1,%2,%3};"
        : "+f"(d[0]), "+f"(d[1]), "+f"(d[2]), "+f"(d[3])
        : "r"(a[0]), "r"(a[1]), "r"(a[2]), "r"(a[3]), "r"(b0), "r"(b1));
}
#define CP_ASYNC16(dst, src) \
    asm volatile("cp.async.cg.shared.global [%0], [%1], 16;" :: "r"(dst), "l"(src))
#define CP_COMMIT() asm volatile("cp.async.commit_group;" ::: "memory")
#define CP_WAIT(n)  asm volatile("cp.async.wait_group %0;" :: "n"(n) : "memory")

__device__ __forceinline__ void cvt_split_store(char* smem, int offHi, int offLo,
                                                uint32_t eoff, float4 v) {
    __nv_bfloat162 h01 = __floats2bfloat162_rn(v.x, v.y);
    __nv_bfloat162 h23 = __floats2bfloat162_rn(v.z, v.w);
    float lx = v.x - __bfloat162float(__low2bfloat16(h01));
    float ly = v.y - __bfloat162float(__high2bfloat16(h01));
    float lz = v.z - __bfloat162float(__low2bfloat16(h23));
    float lw = v.w - __bfloat162float(__high2bfloat16(h23));
    __nv_bfloat162 l01 = __floats2bfloat162_rn(lx, ly);
    __nv_bfloat162 l23 = __floats2bfloat162_rn(lz, lw);
    *(uint2*)(smem + offHi + eoff) = make_uint2(*(uint32_t*)&h01, *(uint32_t*)&h23);
    *(uint2*)(smem + offLo + eoff) = make_uint2(*(uint32_t*)&l01, *(uint32_t*)&l23);
}

#define SA        72

// ---------------- generic 128x128-tile mma GEMM (fused off+attn) -----------
#define OFF_AHI   0
#define OFF_ALO   18432
#define OFF_BHI   36864
#define OFF_BLO   55296
#define SMEM_MMA  73728

__global__ __launch_bounds__(256, 1) void mma_gemm_kernel(
    const float* __restrict__ A,
    const __nv_bfloat16* __restrict__ Bt_hi,
    const __nv_bfloat16* __restrict__ Bt_lo,
    const float* __restrict__ bias,
    float* __restrict__ C, int Nc)
{
    extern __shared__ char smem[];
    const uint32_t sb = smem_u32(smem);
    const int tid   = threadIdx.x;
    const int lane  = tid & 31;
    const int wid   = tid >> 5;
    const int mwarp = wid & 1;
    const int nwarp = wid >> 1;
    const int bn    = blockIdx.x;
    const size_t rowBase = (size_t)blockIdx.y * 128;

    float acc[4][4][4];
#pragma unroll
    for (int i = 0; i < 4; i++)
#pragma unroll
        for (int j = 0; j < 4; j++)
#pragma unroll
            for (int r = 0; r < 4; r++) acc[i][j][r] = 0.f;

    const int a_row = lane & 15, a_kh = lane >> 4;
    const uint32_t aAddrHi = sb + OFF_AHI +
        (uint32_t)(((mwarp * 64 + a_row) * SA + a_kh * 8) * 2);
    const int b_g = lane >> 3, b_r = lane & 7;
    const uint32_t bAddrHi = sb + OFF_BHI +
        (uint32_t)(((nwarp * 32 + (b_g >> 1) * 8 + b_r) * SA + (b_g & 1) * 8) * 2);

#pragma unroll 1
    for (int ch = 0; ch < 4; ch++) {
        const int k0 = ch * 64;
#pragma unroll
        for (int it = 0; it < 8; it++) {
            int idx = tid + it * 256;
            int row = idx >> 4, q = idx & 15;
            float4 v = *(const float4*)(A + (rowBase + row) * 256 + k0 + q * 4);
            cvt_split_store(smem, OFF_AHI, OFF_ALO,
                            (uint32_t)((row * SA + q * 4) * 2), v);
        }
#pragma unroll
        for (int it = 0; it < 4; it++) {
            int idx = tid + it * 256;
            int n = idx >> 3, q = idx & 7;
            uint32_t eoff = (uint32_t)((n * SA + q * 8) * 2);
            size_t goff = (size_t)(bn * 128 + n) * 256 + k0 + q * 8;
            *(uint4*)(smem + OFF_BHI + eoff) = *(const uint4*)(Bt_hi + goff);
            *(uint4*)(smem + OFF_BLO + eoff) = *(const uint4*)(Bt_lo + goff);
        }
        __syncthreads();

#pragma unroll
        for (int ks = 0; ks < 4; ks++) {
            const uint32_t kb = (uint32_t)(ks * 32);
            uint32_t ah[4][4], al[4][4];
#pragma unroll
            for (int mt = 0; mt < 4; mt++) {
                uint32_t ad = aAddrHi + (uint32_t)(mt * 16 * SA * 2) + kb;
                ldsm_x4(ah[mt], ad);
                ldsm_x4(al[mt], ad + (OFF_ALO - OFF_AHI));
            }
            uint32_t bh[2][4], bl[2][4];
#pragma unroll
            for (int pr = 0; pr < 2; pr++) {
                uint32_t bd = bAddrHi + (uint32_t)(pr * 16 * SA * 2) + kb;
                ldsm_x4(bh[pr], bd);
                ldsm_x4(bl[pr], bd + (OFF_BLO - OFF_BHI));
            }
#pragma unroll
            for (int mt = 0; mt < 4; mt++)
#pragma unroll
                for (int nt = 0; nt < 4; nt++) {
                    const int pr = nt >> 1, h = (nt & 1) * 2;
                    mma_bf16(acc[mt][nt], ah[mt], bh[pr][h], bh[pr][h + 1]);
                    mma_bf16(acc[mt][nt], ah[mt], bl[pr][h], bl[pr][h + 1]);
                    mma_bf16(acc[mt][nt], al[mt], bh[pr][h], bh[pr][h + 1]);
                }
        }
        __syncthreads();
    }

#pragma unroll
    for (int nt = 0; nt < 4; nt++) {
        const int col = bn * 128 + nwarp * 32 + nt * 8 + (lane & 3) * 2;
        const float2 bb = *(const float2*)(bias + col);
#pragma unroll
        for (int mt = 0; mt < 4; mt++) {
            const size_t row0 = rowBase + mwarp * 64 + mt * 16 + (lane >> 2);
            float2 o0, o1;
            o0.x = acc[mt][nt][0] + bb.x; o0.y = acc[mt][nt][1] + bb.y;
            o1.x = acc[mt][nt][2] + bb.x; o1.y = acc[mt][nt][3] + bb.y;
            *(float2*)(C + row0 * Nc + col)       = o0;
            *(float2*)(C + (row0 + 8) * Nc + col) = o1;
        }
    }
}

// ------- pipelined 128x256-tile mma GEMM, templated output type ------------
#define V_AHI     0
#define V_ALO     18432
#define V_B0      36864
#define V_BSTRIDE 73728
#define SMEM_V    184320

template <bool HALF_OUT>
__global__ __launch_bounds__(256, 1) void mma_gemm256_kernel(
    const float* __restrict__ A,
    const __nv_bfloat16* __restrict__ Bt_hi,
    const __nv_bfloat16* __restrict__ Bt_lo,
    const float* __restrict__ bias,
    void* __restrict__ Cout)
{
    extern __shared__ char smem[];
    const uint32_t sb = smem_u32(smem);
    const int tid   = threadIdx.x;
    const int lane  = tid & 31;
    const int wid   = tid >> 5;
    const int mwarp = wid & 1;
    const int nwarp = wid >> 1;
    const size_t rowBase = (size_t)blockIdx.x * 128;

    float acc[4][8][4];
#pragma unroll
    for (int i = 0; i < 4; i++)
#pragma unroll
        for (int j = 0; j < 8; j++)
#pragma unroll
            for (int r = 0; r < 4; r++) acc[i][j][r] = 0.f;

    const int a_row = lane & 15, a_kh = lane >> 4;
    const uint32_t aAddrHi = sb + V_AHI +
        (uint32_t)(((mwarp * 64 + a_row) * SA + a_kh * 8) * 2);
    const int b_g = lane >> 3, b_r = lane & 7;
    const uint32_t bAddrBase = sb + V_B0 +
        (uint32_t)(((nwarp * 64 + (b_g >> 1) * 8 + b_r) * SA + (b_g & 1) * 8) * 2);

    float4 apre[8];
#pragma unroll
    for (int it = 0; it < 8; it++) {
        int idx = tid + it * 256;
        int row = idx >> 4, q = idx & 15;
        apre[it] = *(const float4*)(A + (rowBase + row) * 256 + 0 + q * 4);
    }
#pragma unroll
    for (int it = 0; it < 8; it++) {
        int idx = tid + it * 256;
        int n = idx >> 3, q = idx & 7;
        uint32_t eoff = (uint32_t)((n * SA + q * 8) * 2);
        CP_ASYNC16(sb + V_B0 + eoff, Bt_hi + (size_t)n * 256 + q * 8);
        CP_ASYNC16(sb + V_B0 + 36864 + eoff, Bt_lo + (size_t)n * 256 + q * 8);
    }
    CP_COMMIT();

#pragma unroll 1
    for (int ch = 0; ch < 4; ch++) {
        const int buf = ch & 1;
#pragma unroll
        for (int it = 0; it < 8; it++) {
            int idx = tid + it * 256;
            int row = idx >> 4, q = idx & 15;
            cvt_split_store(smem, V_AHI, V_ALO,
                            (uint32_t)((row * SA + q * 4) * 2), apre[it]);
        }
        if (ch < 3) {
            const int k1 = (ch + 1) * 64;
            const uint32_t bsm = sb + V_B0 + (uint32_t)((buf ^ 1) * V_BSTRIDE);
#pragma unroll
            for (int it = 0; it < 8; it++) {
                int idx = tid + it * 256;
                int n = idx >> 3, q = idx & 7;
                uint32_t eoff = (uint32_t)((n * SA + q * 8) * 2);
                CP_ASYNC16(bsm + eoff,         Bt_hi + (size_t)n * 256 + k1 + q * 8);
                CP_ASYNC16(bsm + 36864 + eoff, Bt_lo + (size_t)n * 256 + k1 + q * 8);
            }
            CP_COMMIT();
            CP_WAIT(1);
        } else {
            CP_WAIT(0);
        }
        __syncthreads();

        if (ch < 3) {
            const int k1 = (ch + 1) * 64;
#pragma unroll
            for (int it = 0; it < 8; it++) {
                int idx = tid + it * 256;
                int row = idx >> 4, q = idx & 15;
                apre[it] = *(const float4*)(A + (rowBase + row) * 256 + k1 + q * 4);
            }
        }

        const uint32_t bAddrHi = bAddrBase + (uint32_t)(buf * V_BSTRIDE);
#pragma unroll
        for (int ks = 0; ks < 4; ks++) {
            const uint32_t kb = (uint32_t)(ks * 32);
            uint32_t ah[4][4], al[4][4];
#pragma unroll
            for (int mt = 0; mt < 4; mt++) {
                uint32_t ad = aAddrHi + (uint32_t)(mt * 16 * SA * 2) + kb;
                ldsm_x4(ah[mt], ad);
                ldsm_x4(al[mt], ad + (V_ALO - V_AHI));
            }
#pragma unroll
            for (int pr = 0; pr < 4; pr++) {
                uint32_t bh[4], bl[4];
                uint32_t bd = bAddrHi + (uint32_t)(pr * 16 * SA * 2) + kb;
                ldsm_x4(bh, bd);
                ldsm_x4(bl, bd + 36864);
#pragma unroll
                for (int h2 = 0; h2 < 2; h2++) {
                    const int nt = pr * 2 + h2, h = h2 * 2;
#pragma unroll
                    for (int mt = 0; mt < 4; mt++) {
                        mma_bf16(acc[mt][nt], ah[mt], bh[h], bh[h + 1]);
                        mma_bf16(acc[mt][nt], ah[mt], bl[h], bl[h + 1]);
                        mma_bf16(acc[mt][nt], al[mt], bh[h], bh[h + 1]);
                    }
                }
            }
        }
        __syncthreads();
    }

#pragma unroll
    for (int nt = 0; nt < 8; nt++) {
        const int col = nwarp * 64 + nt * 8 + (lane & 3) * 2;
        const float2 bb = *(const float2*)(bias + col);
#pragma unroll
        for (int mt = 0; mt < 4; mt++) {
            const size_t row0 = rowBase + mwarp * 64 + mt * 16 + (lane >> 2);
            if (HALF_OUT) {
                __half* Ch = (__half*)Cout;
                __half2 h0 = __floats2half2_rn(acc[mt][nt][0] + bb.x,
                                               acc[mt][nt][1] + bb.y);
                __half2 h1 = __floats2half2_rn(acc[mt][nt][2] + bb.x,
                                               acc[mt][nt][3] + bb.y);
                *(__half2*)(Ch + row0 * 256 + col)       = h0;
                *(__half2*)(Ch + (row0 + 8) * 256 + col) = h1;
            } else {
                float* Cf = (float*)Cout;
                float2 o0, o1;
                o0.x = acc[mt][nt][0] + bb.x; o0.y = acc[mt][nt][1] + bb.y;
                o1.x = acc[mt][nt][2] + bb.x; o1.y = acc[mt][nt][3] + bb.y;
                *(float2*)(Cf + row0 * 256 + col)       = o0;
                *(float2*)(Cf + (row0 + 8) * 256 + col) = o1;
            }
        }
    }
}

// ---- unified prep: transposed bf16 splits of all 4 weights + fused bias ----
// rows 0..255 Wv, 256..511 Wout, 512..895 Woff, 896..1023 Wattn
__global__ void prep_all_kernel(const float* __restrict__ Wv,
                                const float* __restrict__ Wout,
                                const float* __restrict__ Woff,
                                const float* __restrict__ Wattn,
                                const float* __restrict__ boff,
                                const float* __restrict__ battn)
{
    int idx = blockIdx.x * 256 + threadIdx.x;   // 0..262143
    int row = idx >> 8, k = idx & 255;
    float v;
    __nv_bfloat16 *dh, *dl;
    int n;
    if (row < 256)      { n = row;       v = Wv  [k * 256 + n]; dh = g_wv_hi;  dl = g_wv_lo;  }
    else if (row < 512) { n = row - 256; v = Wout[k * 256 + n]; dh = g_wo_hi;  dl = g_wo_lo;  }
    else if (row < 896) { n = row - 512; v = Woff[k * 384 + n]; dh = g_wfa_hi; dl = g_wfa_lo; }
    else                { n = row - 896 + 384;
                          v = Wattn[k * 128 + (row - 896)];     dh = g_wfa_hi; dl = g_wfa_lo; }
    __nv_bfloat16 h = __float2bfloat16(v);
    dh[n * 256 + k] = h;
    dl[n * 256 + k] = __float2bfloat16(v - __bfloat162float(h));

    if (blockIdx.x < 2) {
        int t = blockIdx.x * 256 + threadIdx.x;
        g_bfa[t] = (t < 384) ? boff[t] : battn[t - 384];
    }
}

// ====== fused softmax + trilinear deformable sampling (fp16 value) =========
__global__ __launch_bounds__(256) void sample_kernel(
    const float* __restrict__ rp,
    const int*   __restrict__ shapes,
    const int*   __restrict__ starts)
{
    const int q    = blockIdx.x;
    const int h    = threadIdx.x >> 5;
    const int lane = threadIdx.x & 31;

    __shared__ float s_rp[NLEV * 3];
    __shared__ int   s_dim[NLEV * 3];
    __shared__ int   s_start[NLEV];
    if (threadIdx.x < NLEV * 3) {
        s_rp[threadIdx.x]  = rp[(size_t)q * (NLEV * 3) + threadIdx.x];
        s_dim[threadIdx.x] = shapes[threadIdx.x];
    }
    if (threadIdx.x < NLEV) s_start[threadIdx.x] = starts[threadIdx.x];
    __syncthreads();

    const int n = q / LQ;
    const int o     = lane & 15;
    const int chalf = lane >> 4;
    const int l     = o >> 2;

    float logit = g_offattn[(size_t)q * 512 + 384 + h * 16 + o];
    float m = logit;
#pragma unroll
    for (int s = 8; s > 0; s >>= 1)
        m = fmaxf(m, __shfl_xor_sync(0xffffffffu, m, s, 16));
    float e = __expf(logit - m);
    float ssum = e;
#pragma unroll
    for (int s = 8; s > 0; s >>= 1)
        ssum += __shfl_xor_sync(0xffffffffu, ssum, s, 16);
    const float a = e / ssum;

    const float* offq = g_offattn + (size_t)q * 512 + h * 48 + o * 3;
    const int D = s_dim[l * 3 + 0];
    const int H = s_dim[l * 3 + 1];
    const int W = s_dim[l * 3 + 2];
    const float x = (s_rp[l * 3 + 0] + offq[0] / (float)W) * (float)W - 0.5f;
    const float y = (s_rp[l * 3 + 1] + offq[1] / (float)H) * (float)H - 0.5f;
    const float z = (s_rp[l * 3 + 2] + offq[2] / (float)D) * (float)D - 0.5f;
    const float x0f = floorf(x), y0f = floorf(y), z0f = floorf(z);
    const int   x0 = (int)x0f,   y0 = (int)y0f,   z0 = (int)z0f;
    const float fx = x - x0f,    fy = y - y0f,    fz = z - z0f;

    int   idxr[4];
    float awr [4];
#pragma unroll
    for (int cc = 0; cc < 4; cc++) {
        const int c  = chalf * 4 + cc;
        const int dx = c & 1, dy = (c >> 1) & 1, dz = (c >> 2) & 1;
        const int xi = x0 + dx, yi = y0 + dy, zi = z0 + dz;
        const float w = (dx ? fx : 1.f - fx)
                      * (dy ? fy : 1.f - fy)
                      * (dz ? fz : 1.f - fz);
        const bool valid = (xi >= 0) & (xi < W) & (yi >= 0) & (yi < H) &
                           (zi >= 0) & (zi < D) & (w != 0.f);
        idxr[cc] = valid ? ((zi * H + yi) * W + xi) : -1;
        awr[cc]  = a * w;
    }

    const __half* vb[NLEV];
#pragma unroll
    for (int lv = 0; lv < NLEV; lv++)
        vb[lv] = g_value + ((size_t)(n * LEN_IN + s_start[lv])) * DM
               + h * DHEAD + lane;

    float acc0 = 0.f, acc1 = 0.f;
#pragma unroll
    for (int o2 = 0; o2 < 16; o2++) {
        const int lv = o2 >> 2;
#pragma unroll
        for (int c = 0; c < 8; c++) {
            const int src = o2 + (c >> 2) * 16;
            const int cc  = c & 3;
            const int   idx = __shfl_sync(0xffffffffu, idxr[cc], src);
            const float aw  = __shfl_sync(0xffffffffu, awr[cc],  src);
            if (idx >= 0) {
                const float vv = __half2float(__ldg(vb[lv] + (size_t)idx * DM));
                if (c & 1) acc1 = fmaf(aw, vv, acc1);
                else       acc0 = fmaf(aw, vv, acc0);
            }
        }
    }
    g_mid[(size_t)q * DM + h * DHEAD + lane] = acc0 + acc1;
}

// ---------------------------------------------------------------------------
extern "C" void kernel_launch(void* const* d_in, const int* in_sizes, int n_in,
                              void* d_out, int out_size)
{
    const float* query  = (const float*)d_in[0];
    const float* refp   = (const float*)d_in[1];
    const float* inp    = (const float*)d_in[2];
    const int*   shapes = (const int*)  d_in[3];
    const int*   starts = (const int*)  d_in[4];
    const float* Wv     = (const float*)d_in[5];
    const float* bv     = (const float*)d_in[6];
    const float* Woff   = (const float*)d_in[7];
    const float* boff   = (const float*)d_in[8];
    const float* Wattn  = (const float*)d_in[9];
    const float* battn  = (const float*)d_in[10];
    const float* Wout   = (const float*)d_in[11];
    const float* bout   = (const float*)d_in[12];
    float* out = (float*)d_out;

    __half* pv;  float *poa, *pm, *pbfa;
    __nv_bfloat16 *pwvh, *pwvl, *pwoh, *pwol, *pwfah, *pwfal;
    cudaGetSymbolAddress((void**)&pv,  g_value);
    cudaGetSymbolAddress((void**)&poa, g_offattn);
    cudaGetSymbolAddress((void**)&pm,  g_mid);
    cudaGetSymbolAddress((void**)&pbfa, g_bfa);
    cudaGetSymbolAddress((void**)&pwvh, g_wv_hi);
    cudaGetSymbolAddress((void**)&pwvl, g_wv_lo);
    cudaGetSymbolAddress((void**)&pwoh, g_wo_hi);
    cudaGetSymbolAddress((void**)&pwol, g_wo_lo);
    cudaGetSymbolAddress((void**)&pwfah, g_wfa_hi);
    cudaGetSymbolAddress((void**)&pwfal, g_wfa_lo);

    cudaFuncSetAttribute(mma_gemm_kernel,
                         cudaFuncAttributeMaxDynamicSharedMemorySize, SMEM_MMA);
    cudaFuncSetAttribute(mma_gemm256_kernel<true>,
                         cudaFuncAttributeMaxDynamicSharedMemorySize, SMEM_V);
    cudaFuncSetAttribute(mma_gemm256_kernel<false>,
                         cudaFuncAttributeMaxDynamicSharedMemorySize, SMEM_V);

    // 0) prep all transposed bf16 splits + fused bias (one launch)
    prep_all_kernel<<<1024, 256>>>(Wv, Wout, Woff, Wattn, boff, battn);

    // 1) value = input_flatten @ Wv + bv -> fp16  (pipelined 128x256 tile)
    mma_gemm256_kernel<true><<<(NB * LEN_IN) / 128, 256, SMEM_V>>>(
        inp, pwvh, pwvl, bv, pv);

    // 2) [off|attn logits] = query @ [Woff|Wattn] + [boff|battn]  (N=512)
    {
        dim3 grid(4, (NB * LQ) / 128);
        mma_gemm_kernel<<<grid, 256, SMEM_MMA>>>(query, pwfah, pwfal, pbfa, poa, 512);
    }
    // 3) fused softmax + deformable trilinear sampling -> g_mid
    sample_kernel<<<NB * LQ, 256>>>(refp, shapes, starts);

    // 4) out = g_mid @ Wout + bout          (pipelined 128x256 tile, fp32)
    mma_gemm256_kernel<false><<<(NB * LQ) / 128, 256, SMEM_V>>>(
        pm, pwoh, pwol, bout, out);
}